// round 6
// baseline (speedup 1.0000x reference)
#include <cuda_runtime.h>
#include <math.h>
#include <stdint.h>

#define NPTS 16384
#define CD   256
#define KHL  512          // hi|lo concatenated K
#define TOPK 20
#define CAND 40
#define CHUNK 2048
#define NCHUNK (NPTS/CHUNK)
#define CBUF 512

#define SROW 40           // smem row stride (floats), conflict-free for LDS64 frags
#define TILEF (128*SROW)  // floats per operand tile

// -------- scratch (static __device__, no allocations) --------
__device__ float g_xn  [(size_t)NPTS*CD];         // fp32 normalized rows (exact rescore)
__device__ float g_hl  [(size_t)NPTS*KHL];        // k-permuted tf32 hi|lo
__device__ float g_sim [(size_t)CHUNK*NPTS];      // 128 MB
__device__ float g_bmax[(size_t)CHUNK*128];       // per-row per-128col-block max
__device__ int   g_idx [NPTS*TOPK];
__device__ float g_Am  [NPTS*CD];
__device__ float g_Bm  [NPTS*CD];
__device__ float g_R   [NPTS*CD];
__device__ float g_hagg[NPTS*CD];
__device__ float g_H   [NPTS*CD];

static __device__ __forceinline__ float4 ld4(const float* p){
    return *reinterpret_cast<const float4*>(p);
}
static __device__ __forceinline__ uint32_t smem_u32(const void* p){
    uint32_t a;
    asm("{ .reg .u64 t; cvta.to.shared.u64 t, %1; cvt.u32.u64 %0, t; }" : "=r"(a) : "l"(p));
    return a;
}
static __device__ __forceinline__ void cp_async16(uint32_t dst, const void* src){
    asm volatile("cp.async.cg.shared.global [%0], [%1], 16;" :: "r"(dst), "l"(src));
}
static __device__ __forceinline__ void cp_commit(){
    asm volatile("cp.async.commit_group;" ::: "memory");
}
static __device__ __forceinline__ void cp_wait0(){
    asm volatile("cp.async.wait_group 0;" ::: "memory");
}

// ================= row normalize + tf32 split, k-permuted =================
// permutation within each 8-group: j -> (j<4 ? 2j : 2j-7); applied to BOTH
// operands of the contraction, so sim is unchanged.
__global__ __launch_bounds__(256) void rownorm_split_kernel(const float* __restrict__ x){
    int i = blockIdx.x;
    int t = threadIdx.x;
    float v = x[i*CD + t];
    float s = v*v;
    #pragma unroll
    for (int off=16; off; off>>=1) s += __shfl_xor_sync(0xffffffffu, s, off);
    __shared__ float red[8];
    if ((t & 31) == 0) red[t>>5] = s;
    __syncthreads();
    float tot = red[0]+red[1]+red[2]+red[3]+red[4]+red[5]+red[6]+red[7];
    float rn = 1.0f / fmaxf(sqrtf(tot), 1e-8f);
    float xn = v * rn;
    g_xn[(size_t)i*CD + t] = xn;
    uint32_t hb, lb;
    asm("cvt.rna.tf32.f32 %0, %1;" : "=r"(hb) : "f"(xn));
    float hi = __uint_as_float(hb);
    float lo = xn - hi;
    asm("cvt.rna.tf32.f32 %0, %1;" : "=r"(lb) : "f"(lo));
    int j = t & 7;
    int slot = (j < 4) ? (2*j) : (2*j - 7);
    int tp = (t & ~7) | slot;
    g_hl[(size_t)i*KHL + tp]       = hi;
    g_hl[(size_t)i*KHL + 256 + tp] = __uint_as_float(lb);
}

// ================= sim via mma.sync tf32, K=512, 4 warps, 64x64 warp tiles ====
__global__ __launch_bounds__(128,2) void sim_mma_kernel(int rowBase)
{
    extern __shared__ float smem[];
    // [buf][ A: 128*SROW | B: 128*SROW ]
    const uint32_t smem_b = smem_u32(smem);

    const int tid  = threadIdx.x;
    const int warp = tid >> 5, lane = tid & 31;
    const int wr   = warp >> 1;          // 0..1 (m)
    const int wc   = warp & 1;           // 0..1 (n)
    const int g    = lane >> 2;          // 0..7
    const int tg   = lane & 3;           // 0..3

    const size_t rowA0 = (size_t)rowBase + (size_t)blockIdx.y * 128;
    const size_t rowB0 = (size_t)blockIdx.x * 128;
    const float* __restrict__ gA = g_hl + rowA0 * KHL;
    const float* __restrict__ gB = g_hl + rowB0 * KHL;

    float acc[4][8][4];
    #pragma unroll
    for (int mi=0;mi<4;mi++)
        #pragma unroll
        for (int nj=0;nj<8;nj++)
            #pragma unroll
            for (int q=0;q<4;q++) acc[mi][nj][q]=0.f;

    // fill: thread t copies row t of A and row t of B (32 floats = 8 x 16B)
    auto fill = [&](int buf, int kc){
        const int ko = kc*32;
        uint32_t aDst = smem_b + (uint32_t)(buf*2*TILEF + tid*SROW)*4u;
        uint32_t bDst = smem_b + (uint32_t)(buf*2*TILEF + TILEF + tid*SROW)*4u;
        const float* aSrc = gA + (size_t)tid*KHL + ko;
        const float* bSrc = gB + (size_t)tid*KHL + ko;
        #pragma unroll
        for (int q=0;q<8;q++){
            cp_async16(aDst + q*16u, aSrc + q*4);
            cp_async16(bDst + q*16u, bSrc + q*4);
        }
    };

    fill(0, 0); cp_commit();

    int buf = 0;
    #pragma unroll 1
    for (int kc = 0; kc < 16; kc++){
        cp_wait0();
        __syncthreads();
        if (kc < 15){ fill(buf^1, kc+1); cp_commit(); }

        const float* Ab = smem + buf*2*TILEF + (wr*64)*SROW;
        const float* Bb = smem + buf*2*TILEF + TILEF + (wc*64)*SROW;
        #pragma unroll
        for (int k8=0;k8<4;k8++){
            const int kb = k8*8 + 2*tg;
            uint32_t a[4][4];
            #pragma unroll
            for (int mi=0;mi<4;mi++){
                float2 p0 = *(const float2*)&Ab[(mi*16+g  )*SROW + kb];
                float2 p1 = *(const float2*)&Ab[(mi*16+g+8)*SROW + kb];
                a[mi][0]=__float_as_uint(p0.x); a[mi][1]=__float_as_uint(p1.x);
                a[mi][2]=__float_as_uint(p0.y); a[mi][3]=__float_as_uint(p1.y);
            }
            #pragma unroll
            for (int nj=0;nj<8;nj++){
                float2 pb = *(const float2*)&Bb[(nj*8+g)*SROW + kb];
                uint32_t b0=__float_as_uint(pb.x), b1=__float_as_uint(pb.y);
                #pragma unroll
                for (int mi=0;mi<4;mi++){
                    asm volatile(
                        "mma.sync.aligned.m16n8k8.row.col.f32.tf32.tf32.f32 "
                        "{%0,%1,%2,%3}, {%4,%5,%6,%7}, {%8,%9}, {%0,%1,%2,%3};"
                        : "+f"(acc[mi][nj][0]), "+f"(acc[mi][nj][1]),
                          "+f"(acc[mi][nj][2]), "+f"(acc[mi][nj][3])
                        : "r"(a[mi][0]), "r"(a[mi][1]), "r"(a[mi][2]), "r"(a[mi][3]),
                          "r"(b0), "r"(b1));
                }
            }
        }
        __syncthreads();
        buf ^= 1;
    }

    // ---- store C ----
    float* C = g_sim + ((size_t)blockIdx.y*128 + wr*64 + g) * NPTS
                     + rowB0 + wc*64 + 2*tg;
    #pragma unroll
    for (int mi=0;mi<4;mi++){
        #pragma unroll
        for (int nj=0;nj<8;nj++){
            float* c0 = C + (size_t)(mi*16)*NPTS + nj*8;
            *(float2*)c0                     = make_float2(acc[mi][nj][0], acc[mi][nj][1]);
            *(float2*)(c0 + (size_t)8*NPTS)  = make_float2(acc[mi][nj][2], acc[mi][nj][3]);
        }
    }

    // ---- per-row tile max -> g_bmax ----
    float* sb = smem;   // reuse: [128][2]
    #pragma unroll
    for (int mi=0;mi<4;mi++){
        float r0 = -1e30f, r1 = -1e30f;
        #pragma unroll
        for (int nj=0;nj<8;nj++){
            r0 = fmaxf(r0, fmaxf(acc[mi][nj][0], acc[mi][nj][1]));
            r1 = fmaxf(r1, fmaxf(acc[mi][nj][2], acc[mi][nj][3]));
        }
        #pragma unroll
        for (int off=1; off<4; off<<=1){
            r0 = fmaxf(r0, __shfl_xor_sync(0xffffffffu, r0, off));
            r1 = fmaxf(r1, __shfl_xor_sync(0xffffffffu, r1, off));
        }
        if (tg == 0){
            sb[(wr*64 + mi*16 + g  )*2 + wc] = r0;
            sb[(wr*64 + mi*16 + g+8)*2 + wc] = r1;
        }
    }
    __syncthreads();
    if (tid < 128){
        float bm = fmaxf(sb[tid*2], sb[tid*2+1]);
        g_bmax[(size_t)(blockIdx.y*128 + tid)*128 + blockIdx.x] = bm;
    }
}

// ================= top-20: block-max filter + exact fp32 rescore =================
__global__ __launch_bounds__(256) void topk_kernel(int rowBase)
{
    const int row  = blockIdx.x;           // chunk-local
    const int rowG = rowBase + row;
    const float* __restrict__ S  = g_sim  + (size_t)row * NPTS;
    const float* __restrict__ BM = g_bmax + (size_t)row * 128;
    const int tid = threadIdx.x;
    const int lane = tid & 31, warp = tid >> 5;

    __shared__ float s_tau;
    __shared__ int   s_cnt, s_bcnt;
    __shared__ int   blist[128];
    __shared__ float cv[CBUF];
    __shared__ int   ci[CBUF];
    __shared__ float xi[CD];

    xi[tid] = g_xn[(size_t)rowG*CD + tid];
    if (tid == 0){ s_cnt = 0; s_bcnt = 0; }
    __syncthreads();

    // tau = CAND-th largest of the 128 block maxima (valid top-CAND filter)
    if (warp == 0){
        float a[4];
        #pragma unroll
        for (int j=0;j<4;j++) a[j] = BM[lane*4 + j];
        #define CSW(i,j) { if (a[i] < a[j]) { float t=a[i]; a[i]=a[j]; a[j]=t; } }
        CSW(0,1) CSW(2,3) CSW(0,2) CSW(1,3) CSW(1,2)
        #undef CSW
        float tau = -1e30f;
        for (int sel = 0; sel < CAND; sel++){
            float h = a[0];
            float bv = h;
            #pragma unroll
            for (int off=16; off; off>>=1)
                bv = fmaxf(bv, __shfl_xor_sync(0xffffffffu, bv, off));
            unsigned ball = __ballot_sync(0xffffffffu, h == bv);
            if (lane == (__ffs(ball) - 1)){
                #pragma unroll
                for (int j=0;j<3;j++) a[j] = a[j+1];
                a[3] = -1e30f;
            }
            tau = bv;
        }
        if (lane == 0) s_tau = tau;
    }
    __syncthreads();
    const float tau = s_tau;

    // qualifying block list
    if (tid < 128){
        if (BM[tid] >= tau){ int p = atomicAdd(&s_bcnt, 1); blist[p] = tid; }
    }
    __syncthreads();
    const int bcnt = s_bcnt;

    // collect candidates from qualifying blocks only (2 blocks per pass)
    for (int i = (tid >> 7); i < bcnt; i += 2){
        const int b = blist[i];
        const int t = tid & 127;
        float v = S[b*128 + t];
        if (v >= tau){
            int p = atomicAdd(&s_cnt, 1);
            if (p < CBUF) ci[p] = b*128 + t;
        }
    }
    __syncthreads();
    int cnt = s_cnt < CBUF ? s_cnt : CBUF;

    // exact fp32 rescore (serial k-ascending fmaf — matches reference selections)
    for (int p = tid; p < cnt; p += 256){
        const float* __restrict__ xj = g_xn + (size_t)ci[p]*CD;
        float acc = 0.f;
        #pragma unroll 8
        for (int k = 0; k < CD; k++)
            acc = fmaf(xi[k], xj[k], acc);
        cv[p] = acc;
    }
    __syncthreads();

    // warp 0 selects top-20 by exact values (tie-break: lowest index)
    if (warp == 0){
        for (int sel = 0; sel < TOPK; sel++){
            float bv = -1e30f; int bi = 0x7fffffff; int bp = -1;
            for (int p = lane; p < cnt; p += 32){
                float vv = cv[p]; int ii = ci[p];
                if (vv > bv || (vv == bv && ii < bi)){ bv = vv; bi = ii; bp = p; }
            }
            #pragma unroll
            for (int off=16; off; off>>=1){
                float ov = __shfl_xor_sync(0xffffffffu, bv, off);
                int   oi = __shfl_xor_sync(0xffffffffu, bi, off);
                int   op = __shfl_xor_sync(0xffffffffu, bp, off);
                if (ov > bv || (ov == bv && oi < bi)){ bv = ov; bi = oi; bp = op; }
            }
            if (lane == 0){
                g_idx[(size_t)rowG*TOPK + sel] = bi;
                cv[bp] = -1e30f;
            }
            __syncwarp();
        }
    }
}

// ================= gather + relu + sum over 20 neighbors =================
__global__ __launch_bounds__(256) void gather_relu_sum_kernel(){
    const int i = blockIdx.x, c = threadIdx.x;
    __shared__ int nb[TOPK];
    if (c < TOPK) nb[c] = g_idx[(size_t)i*TOPK + c];
    __syncthreads();
    float a = g_Am[(size_t)i*CD + c];
    float acc = 0.f;
    #pragma unroll
    for (int k=0;k<TOPK;k++)
        acc += fmaxf(a + g_Bm[(size_t)nb[k]*CD + c], 0.f);
    g_R[(size_t)i*CD + c] = acc;
}

// ================= generic MLP GEMM =================
__global__ __launch_bounds__(256,2) void mlp_gemm_kernel(
    const float* __restrict__ A1, const float* __restrict__ A2,
    const float* __restrict__ W, int nslab,
    const float* __restrict__ bias, float biasScale,
    int doRelu, const float* __restrict__ res,
    float* __restrict__ Cout)
{
    __shared__ float As[2][16][132];
    __shared__ float Bs[2][16][132];
    const int tid = threadIdx.x;
    const int r0 = tid >> 2, kq = (tid & 3) << 2;
    const int kr0 = tid >> 5, nq = (tid & 31) << 2;
    const int tx = tid & 15, ty = tid >> 4;
    const int m0 = tx*8, n0 = ty*8;

    const size_t rowOff = (size_t)blockIdx.y*128*CD;
    const float* A1b = A1 + rowOff;
    const float* A2b = A2 ? (A2 + rowOff) : A1b;
    const float* Wb  = W + blockIdx.x*128;

    float acc[8][8];
    #pragma unroll
    for (int i=0;i<8;i++)
        #pragma unroll
        for (int j=0;j<8;j++) acc[i][j]=0.f;

    float4 va0 = ld4(A1b + r0*CD + kq);
    float4 va1 = ld4(A1b + (r0+64)*CD + kq);
    float4 vb0 = ld4(Wb + (size_t)kr0*CD + nq);
    float4 vb1 = ld4(Wb + (size_t)(kr0+8)*CD + nq);

    As[0][kq+0][r0]=va0.x; As[0][kq+1][r0]=va0.y; As[0][kq+2][r0]=va0.z; As[0][kq+3][r0]=va0.w;
    As[0][kq+0][r0+64]=va1.x; As[0][kq+1][r0+64]=va1.y; As[0][kq+2][r0+64]=va1.z; As[0][kq+3][r0+64]=va1.w;
    *(float4*)&Bs[0][kr0  ][nq] = vb0;
    *(float4*)&Bs[0][kr0+8][nq] = vb1;
    __syncthreads();

    int buf = 0;
    for (int s=0; s<nslab; s++){
        if (s+1 < nslab){
            int kk = (s+1)*16;
            const float* Ag = (kk < 256) ? (A1b + kk) : (A2b + (kk-256));
            va0 = ld4(Ag + r0*CD + kq);
            va1 = ld4(Ag + (r0+64)*CD + kq);
            vb0 = ld4(Wb + (size_t)(kk+kr0)*CD + nq);
            vb1 = ld4(Wb + (size_t)(kk+kr0+8)*CD + nq);
        }
        #pragma unroll
        for (int k=0;k<16;k++){
            float4 a0 = *(const float4*)&As[buf][k][m0];
            float4 a1 = *(const float4*)&As[buf][k][m0+4];
            float4 b0 = *(const float4*)&Bs[buf][k][n0];
            float4 b1 = *(const float4*)&Bs[buf][k][n0+4];
            float av[8] = {a0.x,a0.y,a0.z,a0.w,a1.x,a1.y,a1.z,a1.w};
            float bw[8] = {b0.x,b0.y,b0.z,b0.w,b1.x,b1.y,b1.z,b1.w};
            #pragma unroll
            for (int i=0;i<8;i++)
                #pragma unroll
                for (int j=0;j<8;j++)
                    acc[i][j] = fmaf(av[i], bw[j], acc[i][j]);
        }
        if (s+1 < nslab){
            int nb = buf ^ 1;
            As[nb][kq+0][r0]=va0.x; As[nb][kq+1][r0]=va0.y; As[nb][kq+2][r0]=va0.z; As[nb][kq+3][r0]=va0.w;
            As[nb][kq+0][r0+64]=va1.x; As[nb][kq+1][r0+64]=va1.y; As[nb][kq+2][r0+64]=va1.z; As[nb][kq+3][r0+64]=va1.w;
            *(float4*)&Bs[nb][kr0  ][nq] = vb0;
            *(float4*)&Bs[nb][kr0+8][nq] = vb1;
            __syncthreads();
            buf = nb;
        }
    }

    float bv_[8];
    if (bias){
        float4 t0 = ld4(bias + blockIdx.x*128 + n0);
        float4 t1 = ld4(bias + blockIdx.x*128 + n0 + 4);
        bv_[0]=t0.x*biasScale; bv_[1]=t0.y*biasScale; bv_[2]=t0.z*biasScale; bv_[3]=t0.w*biasScale;
        bv_[4]=t1.x*biasScale; bv_[5]=t1.y*biasScale; bv_[6]=t1.z*biasScale; bv_[7]=t1.w*biasScale;
    } else {
        #pragma unroll
        for (int j=0;j<8;j++) bv_[j]=0.f;
    }

    float* Cb = Cout + (size_t)blockIdx.y*128*CD + blockIdx.x*128;
    const float* Rb = res ? (res + (size_t)blockIdx.y*128*CD + blockIdx.x*128) : nullptr;
    #pragma unroll
    for (int i=0;i<8;i++){
        float o[8];
        #pragma unroll
        for (int j=0;j<8;j++){
            float t = acc[i][j] + bv_[j];
            if (doRelu) t = fmaxf(t, 0.f);
            o[j] = t;
        }
        if (Rb){
            float4 q0 = ld4(Rb + (size_t)(m0+i)*CD + n0);
            float4 q1 = ld4(Rb + (size_t)(m0+i)*CD + n0 + 4);
            o[0]+=q0.x; o[1]+=q0.y; o[2]+=q0.z; o[3]+=q0.w;
            o[4]+=q1.x; o[5]+=q1.y; o[6]+=q1.z; o[7]+=q1.w;
        }
        *(float4*)&Cb[(size_t)(m0+i)*CD + n0  ] = make_float4(o[0],o[1],o[2],o[3]);
        *(float4*)&Cb[(size_t)(m0+i)*CD + n0+4] = make_float4(o[4],o[5],o[6],o[7]);
    }
}

// ================= launch =================
extern "C" void kernel_launch(void* const* d_in, const int* in_sizes, int n_in,
                              void* d_out, int out_size)
{
    const float* x   = (const float*)d_in[0];
    const float* W1m = (const float*)d_in[1];
    const float* b1m = (const float*)d_in[2];
    const float* W2m = (const float*)d_in[3];
    const float* b2m = (const float*)d_in[4];
    const float* W1u = (const float*)d_in[5];
    const float* b1u = (const float*)d_in[6];
    const float* W2u = (const float*)d_in[7];
    const float* b2u = (const float*)d_in[8];
    float* out = (float*)d_out;

    float *p_Am=nullptr, *p_Bm=nullptr, *p_R=nullptr, *p_hagg=nullptr, *p_H=nullptr;
    cudaGetSymbolAddress((void**)&p_Am,   g_Am);
    cudaGetSymbolAddress((void**)&p_Bm,   g_Bm);
    cudaGetSymbolAddress((void**)&p_R,    g_R);
    cudaGetSymbolAddress((void**)&p_hagg, g_hagg);
    cudaGetSymbolAddress((void**)&p_H,    g_H);

    const int SIM_SMEM = 4 * TILEF * (int)sizeof(float);   // 2 buf x (A+B) = 81920 B
    cudaFuncSetAttribute(sim_mma_kernel, cudaFuncAttributeMaxDynamicSharedMemorySize, SIM_SMEM);

    rownorm_split_kernel<<<NPTS, 256>>>(x);

    // A_msg = x @ W1_msg[0:256] + b1_msg ; B_msg = x @ W1_msg[256:512]
    mlp_gemm_kernel<<<dim3(2,128), 256>>>(x, nullptr, W1m,          16, b1m, 1.f, 0, nullptr, p_Am);
    mlp_gemm_kernel<<<dim3(2,128), 256>>>(x, nullptr, W1m + 256*CD, 16, nullptr, 0.f, 0, nullptr, p_Bm);

    // sim + topk in row chunks
    for (int cb = 0; cb < NCHUNK; cb++){
        sim_mma_kernel<<<dim3(NPTS/128, CHUNK/128), 128, SIM_SMEM>>>(cb*CHUNK);
        topk_kernel  <<<CHUNK, 256>>>(cb*CHUNK);
    }

    // R_i = sum_j relu(A_i + B_j)
    gather_relu_sum_kernel<<<NPTS, 256>>>();

    // h_agg = R @ W2_msg + 20*b2_msg
    mlp_gemm_kernel<<<dim3(2,128), 256>>>(p_R, nullptr, W2m, 16, b2m, (float)TOPK, 0, nullptr, p_hagg);

    // H = relu(x @ W1u[0:256] + h_agg @ W1u[256:512] + b1u)
    mlp_gemm_kernel<<<dim3(2,128), 256>>>(x, p_hagg, W1u, 32, b1u, 1.f, 1, nullptr, p_H);

    // out = x + H @ W2_upd + b2_upd
    mlp_gemm_kernel<<<dim3(2,128), 256>>>(p_H, nullptr, W2u, 16, b2u, 1.f, 0, x, out);
}

// round 7
// speedup vs baseline: 1.3885x; 1.3885x over previous
#include <cuda_runtime.h>
#include <math.h>
#include <stdint.h>

#define NPTS 16384
#define CD   256
#define KHL  512          // hi|lo concatenated K
#define TOPK 20
#define CAND 40
#define CHUNK 2048
#define NCHUNK (NPTS/CHUNK)
#define CBUF 512

#define SROW 36           // padded smem row stride (floats)
#define TILE (128*SROW)

// -------- scratch (static __device__, no allocations) --------
__device__ float g_xn  [(size_t)NPTS*CD];         // fp32 normalized rows (exact rescore)
__device__ float g_hl  [(size_t)NPTS*KHL];        // [:,0:256]=hi tf32, [:,256:512]=lo tf32
__device__ float g_sim [(size_t)CHUNK*NPTS];      // 128 MB
__device__ float g_bmax[(size_t)CHUNK*128];       // per-row per-128col-block max
__device__ int   g_idx [NPTS*TOPK];
__device__ float g_Am  [NPTS*CD];
__device__ float g_Bm  [NPTS*CD];
__device__ float g_R   [NPTS*CD];
__device__ float g_hagg[NPTS*CD];
__device__ float g_H   [NPTS*CD];

static __device__ __forceinline__ float4 ld4(const float* p){
    return *reinterpret_cast<const float4*>(p);
}

// ================= row normalize + tf32 split (hi | lo) =================
__global__ __launch_bounds__(256) void rownorm_split_kernel(const float* __restrict__ x){
    int i = blockIdx.x;
    int t = threadIdx.x;
    float v = x[i*CD + t];
    float s = v*v;
    #pragma unroll
    for (int off=16; off; off>>=1) s += __shfl_xor_sync(0xffffffffu, s, off);
    __shared__ float red[8];
    if ((t & 31) == 0) red[t>>5] = s;
    __syncthreads();
    float tot = red[0]+red[1]+red[2]+red[3]+red[4]+red[5]+red[6]+red[7];
    float rn = 1.0f / fmaxf(sqrtf(tot), 1e-8f);
    float xn = v * rn;
    g_xn[(size_t)i*CD + t] = xn;
    uint32_t hb, lb;
    asm("cvt.rna.tf32.f32 %0, %1;" : "=r"(hb) : "f"(xn));
    float hi = __uint_as_float(hb);
    float lo = xn - hi;
    asm("cvt.rna.tf32.f32 %0, %1;" : "=r"(lb) : "f"(lo));
    g_hl[(size_t)i*KHL + t]       = hi;
    g_hl[(size_t)i*KHL + 256 + t] = __uint_as_float(lb);
}

// ================= sim via mma.sync tf32, K=512 (round-5 proven shape) =======
// Block tile 128x128, 8 warps in 4(m) x 2(n), warp tile 32x64 (m16n8k8 frags).
// Epilogue additionally writes per-row 128-col-block maxima to g_bmax.
__global__ __launch_bounds__(256,2) void sim_mma_kernel(int rowBase)
{
    extern __shared__ float smem[];
    float* As = smem;              // [2][128][SROW]
    float* Bs = smem + 2*TILE;     // [2][128][SROW]

    const int tid  = threadIdx.x;
    const int warp = tid >> 5, lane = tid & 31;
    const int wr   = warp >> 1;          // 0..3 (m)
    const int wc   = warp & 1;           // 0..1 (n)
    const int g    = lane >> 2;          // 0..7
    const int tg   = lane & 3;           // 0..3

    const size_t rowA0 = (size_t)rowBase + (size_t)blockIdx.y * 128;
    const size_t rowB0 = (size_t)blockIdx.x * 128;
    const float* __restrict__ gA = g_hl + rowA0 * KHL;
    const float* __restrict__ gB = g_hl + rowB0 * KHL;

    float acc[2][8][4];
    #pragma unroll
    for (int mi=0;mi<2;mi++)
        #pragma unroll
        for (int nj=0;nj<8;nj++)
            #pragma unroll
            for (int q=0;q<4;q++) acc[mi][nj][q]=0.f;

    const int fr[4] = { (tid + 0)   >> 3, (tid + 256) >> 3, (tid + 512) >> 3, (tid + 768) >> 3 };
    const int fc = (tid & 7) * 4;

    // prologue: fill buf 0 for kc=0
    #pragma unroll
    for (int p=0;p<4;p++){
        *(float4*)&As[fr[p]*SROW + fc] = ld4(gA + (size_t)fr[p]*KHL + fc);
        *(float4*)&Bs[fr[p]*SROW + fc] = ld4(gB + (size_t)fr[p]*KHL + fc);
    }
    __syncthreads();

    int buf = 0;
    #pragma unroll 1
    for (int kc = 0; kc < 16; kc++){
        float4 va[4], vb[4];
        if (kc < 15){
            const int ko = (kc+1)*32 + fc;
            #pragma unroll
            for (int p=0;p<4;p++){
                va[p] = ld4(gA + (size_t)fr[p]*KHL + ko);
                vb[p] = ld4(gB + (size_t)fr[p]*KHL + ko);
            }
        }

        const float* Ab = &As[buf*TILE + (wr*32)*SROW];
        const float* Bb = &Bs[buf*TILE + (wc*64)*SROW];
        #pragma unroll
        for (int k8=0;k8<4;k8++){
            const int kb = k8*8;
            uint32_t a[2][4];
            #pragma unroll
            for (int mi=0;mi<2;mi++){
                const float* ap = Ab + (mi*16)*SROW + kb;
                a[mi][0] = __float_as_uint(ap[(g  )*SROW + tg  ]);
                a[mi][1] = __float_as_uint(ap[(g+8)*SROW + tg  ]);
                a[mi][2] = __float_as_uint(ap[(g  )*SROW + tg+4]);
                a[mi][3] = __float_as_uint(ap[(g+8)*SROW + tg+4]);
            }
            #pragma unroll
            for (int nj=0;nj<8;nj++){
                const float* bp = Bb + (nj*8)*SROW + kb;
                uint32_t b0 = __float_as_uint(bp[g*SROW + tg  ]);
                uint32_t b1 = __float_as_uint(bp[g*SROW + tg+4]);
                #pragma unroll
                for (int mi=0;mi<2;mi++){
                    asm volatile(
                        "mma.sync.aligned.m16n8k8.row.col.f32.tf32.tf32.f32 "
                        "{%0,%1,%2,%3}, {%4,%5,%6,%7}, {%8,%9}, {%0,%1,%2,%3};"
                        : "+f"(acc[mi][nj][0]), "+f"(acc[mi][nj][1]),
                          "+f"(acc[mi][nj][2]), "+f"(acc[mi][nj][3])
                        : "r"(a[mi][0]), "r"(a[mi][1]), "r"(a[mi][2]), "r"(a[mi][3]),
                          "r"(b0), "r"(b1));
                }
            }
        }

        if (kc < 15){
            const int nb = buf ^ 1;
            #pragma unroll
            for (int p=0;p<4;p++){
                *(float4*)&As[nb*TILE + fr[p]*SROW + fc] = va[p];
                *(float4*)&Bs[nb*TILE + fr[p]*SROW + fc] = vb[p];
            }
            __syncthreads();
            buf = nb;
        }
    }

    // ---- store C ----
    float* C = g_sim + ((size_t)blockIdx.y*128 + wr*32 + g) * NPTS
                     + rowB0 + wc*64 + 2*tg;
    #pragma unroll
    for (int mi=0;mi<2;mi++){
        #pragma unroll
        for (int nj=0;nj<8;nj++){
            float* c0 = C + (size_t)(mi*16)*NPTS + nj*8;
            *(float2*)c0                     = make_float2(acc[mi][nj][0], acc[mi][nj][1]);
            *(float2*)(c0 + (size_t)8*NPTS)  = make_float2(acc[mi][nj][2], acc[mi][nj][3]);
        }
    }

    // ---- per-row 128-col-block max -> g_bmax ----
    __syncthreads();                 // smem buffers no longer needed; reuse
    float* sb = smem;                // [128][2]
    #pragma unroll
    for (int mi=0;mi<2;mi++){
        float r0 = -1e30f, r1 = -1e30f;
        #pragma unroll
        for (int nj=0;nj<8;nj++){
            r0 = fmaxf(r0, fmaxf(acc[mi][nj][0], acc[mi][nj][1]));
            r1 = fmaxf(r1, fmaxf(acc[mi][nj][2], acc[mi][nj][3]));
        }
        // reduce across tg (lanes g*4 + {0..3})
        #pragma unroll
        for (int off=1; off<4; off<<=1){
            r0 = fmaxf(r0, __shfl_xor_sync(0xffffffffu, r0, off));
            r1 = fmaxf(r1, __shfl_xor_sync(0xffffffffu, r1, off));
        }
        if (tg == 0){
            sb[(wr*32 + mi*16 + g  )*2 + wc] = r0;
            sb[(wr*32 + mi*16 + g+8)*2 + wc] = r1;
        }
    }
    __syncthreads();
    if (tid < 128){
        float bm = fmaxf(sb[tid*2], sb[tid*2+1]);
        g_bmax[(size_t)(blockIdx.y*128 + tid)*128 + blockIdx.x] = bm;
    }
}

// ================= top-20: block-max filter + exact fp32 rescore =================
__global__ __launch_bounds__(256) void topk_kernel(int rowBase)
{
    const int row  = blockIdx.x;           // chunk-local
    const int rowG = rowBase + row;
    const float* __restrict__ S  = g_sim  + (size_t)row * NPTS;
    const float* __restrict__ BM = g_bmax + (size_t)row * 128;
    const int tid = threadIdx.x;
    const int lane = tid & 31, warp = tid >> 5;

    __shared__ float s_tau;
    __shared__ int   s_cnt, s_bcnt;
    __shared__ int   blist[128];
    __shared__ float cv[CBUF];
    __shared__ int   ci[CBUF];
    __shared__ float xi[CD];

    xi[tid] = g_xn[(size_t)rowG*CD + tid];
    if (tid == 0){ s_cnt = 0; s_bcnt = 0; }
    __syncthreads();

    // tau = CAND-th largest of the 128 block maxima (valid top-CAND filter)
    if (warp == 0){
        float a[4];
        #pragma unroll
        for (int j=0;j<4;j++) a[j] = BM[lane*4 + j];
        #define CSW(i,j) { if (a[i] < a[j]) { float t=a[i]; a[i]=a[j]; a[j]=t; } }
        CSW(0,1) CSW(2,3) CSW(0,2) CSW(1,3) CSW(1,2)
        #undef CSW
        float tau = -1e30f;
        for (int sel = 0; sel < CAND; sel++){
            float h = a[0];
            float bv = h;
            #pragma unroll
            for (int off=16; off; off>>=1)
                bv = fmaxf(bv, __shfl_xor_sync(0xffffffffu, bv, off));
            unsigned ball = __ballot_sync(0xffffffffu, h == bv);
            if (lane == (__ffs(ball) - 1)){
                #pragma unroll
                for (int j=0;j<3;j++) a[j] = a[j+1];
                a[3] = -1e30f;
            }
            tau = bv;
        }
        if (lane == 0) s_tau = tau;
    }
    __syncthreads();
    const float tau = s_tau;

    // qualifying block list
    if (tid < 128){
        if (BM[tid] >= tau){ int p = atomicAdd(&s_bcnt, 1); blist[p] = tid; }
    }
    __syncthreads();
    const int bcnt = s_bcnt;

    // collect candidates from qualifying blocks only (2 blocks per pass)
    for (int i = (tid >> 7); i < bcnt; i += 2){
        const int b = blist[i];
        const int t = tid & 127;
        float v = S[b*128 + t];
        if (v >= tau){
            int p = atomicAdd(&s_cnt, 1);
            if (p < CBUF) ci[p] = b*128 + t;
        }
    }
    __syncthreads();
    int cnt = s_cnt < CBUF ? s_cnt : CBUF;

    // exact fp32 rescore (serial k-ascending fmaf — matches reference selections)
    for (int p = tid; p < cnt; p += 256){
        const float* __restrict__ xj = g_xn + (size_t)ci[p]*CD;
        float acc = 0.f;
        #pragma unroll 8
        for (int k = 0; k < CD; k++)
            acc = fmaf(xi[k], xj[k], acc);
        cv[p] = acc;
    }
    __syncthreads();

    // warp 0 selects top-20 by exact values (tie-break: lowest index)
    if (warp == 0){
        for (int sel = 0; sel < TOPK; sel++){
            float bv = -1e30f; int bi = 0x7fffffff; int bp = -1;
            for (int p = lane; p < cnt; p += 32){
                float vv = cv[p]; int ii = ci[p];
                if (vv > bv || (vv == bv && ii < bi)){ bv = vv; bi = ii; bp = p; }
            }
            #pragma unroll
            for (int off=16; off; off>>=1){
                float ov = __shfl_xor_sync(0xffffffffu, bv, off);
                int   oi = __shfl_xor_sync(0xffffffffu, bi, off);
                int   op = __shfl_xor_sync(0xffffffffu, bp, off);
                if (ov > bv || (ov == bv && oi < bi)){ bv = ov; bi = oi; bp = op; }
            }
            if (lane == 0){
                g_idx[(size_t)rowG*TOPK + sel] = bi;
                cv[bp] = -1e30f;
            }
            __syncwarp();
        }
    }
}

// ================= gather + relu + sum over 20 neighbors =================
__global__ __launch_bounds__(256) void gather_relu_sum_kernel(){
    const int i = blockIdx.x, c = threadIdx.x;
    __shared__ int nb[TOPK];
    if (c < TOPK) nb[c] = g_idx[(size_t)i*TOPK + c];
    __syncthreads();
    float a = g_Am[(size_t)i*CD + c];
    float acc = 0.f;
    #pragma unroll
    for (int k=0;k<TOPK;k++)
        acc += fmaxf(a + g_Bm[(size_t)nb[k]*CD + c], 0.f);
    g_R[(size_t)i*CD + c] = acc;
}

// ================= generic MLP GEMM =================
__global__ __launch_bounds__(256,2) void mlp_gemm_kernel(
    const float* __restrict__ A1, const float* __restrict__ A2,
    const float* __restrict__ W, int nslab,
    const float* __restrict__ bias, float biasScale,
    int doRelu, const float* __restrict__ res,
    float* __restrict__ Cout)
{
    __shared__ float As[2][16][132];
    __shared__ float Bs[2][16][132];
    const int tid = threadIdx.x;
    const int r0 = tid >> 2, kq = (tid & 3) << 2;
    const int kr0 = tid >> 5, nq = (tid & 31) << 2;
    const int tx = tid & 15, ty = tid >> 4;
    const int m0 = tx*8, n0 = ty*8;

    const size_t rowOff = (size_t)blockIdx.y*128*CD;
    const float* A1b = A1 + rowOff;
    const float* A2b = A2 ? (A2 + rowOff) : A1b;
    const float* Wb  = W + blockIdx.x*128;

    float acc[8][8];
    #pragma unroll
    for (int i=0;i<8;i++)
        #pragma unroll
        for (int j=0;j<8;j++) acc[i][j]=0.f;

    float4 va0 = ld4(A1b + r0*CD + kq);
    float4 va1 = ld4(A1b + (r0+64)*CD + kq);
    float4 vb0 = ld4(Wb + (size_t)kr0*CD + nq);
    float4 vb1 = ld4(Wb + (size_t)(kr0+8)*CD + nq);

    As[0][kq+0][r0]=va0.x; As[0][kq+1][r0]=va0.y; As[0][kq+2][r0]=va0.z; As[0][kq+3][r0]=va0.w;
    As[0][kq+0][r0+64]=va1.x; As[0][kq+1][r0+64]=va1.y; As[0][kq+2][r0+64]=va1.z; As[0][kq+3][r0+64]=va1.w;
    *(float4*)&Bs[0][kr0  ][nq] = vb0;
    *(float4*)&Bs[0][kr0+8][nq] = vb1;
    __syncthreads();

    int buf = 0;
    for (int s=0; s<nslab; s++){
        if (s+1 < nslab){
            int kk = (s+1)*16;
            const float* Ag = (kk < 256) ? (A1b + kk) : (A2b + (kk-256));
            va0 = ld4(Ag + r0*CD + kq);
            va1 = ld4(Ag + (r0+64)*CD + kq);
            vb0 = ld4(Wb + (size_t)(kk+kr0)*CD + nq);
            vb1 = ld4(Wb + (size_t)(kk+kr0+8)*CD + nq);
        }
        #pragma unroll
        for (int k=0;k<16;k++){
            float4 a0 = *(const float4*)&As[buf][k][m0];
            float4 a1 = *(const float4*)&As[buf][k][m0+4];
            float4 b0 = *(const float4*)&Bs[buf][k][n0];
            float4 b1 = *(const float4*)&Bs[buf][k][n0+4];
            float av[8] = {a0.x,a0.y,a0.z,a0.w,a1.x,a1.y,a1.z,a1.w};
            float bw[8] = {b0.x,b0.y,b0.z,b0.w,b1.x,b1.y,b1.z,b1.w};
            #pragma unroll
            for (int i=0;i<8;i++)
                #pragma unroll
                for (int j=0;j<8;j++)
                    acc[i][j] = fmaf(av[i], bw[j], acc[i][j]);
        }
        if (s+1 < nslab){
            int nb = buf ^ 1;
            As[nb][kq+0][r0]=va0.x; As[nb][kq+1][r0]=va0.y; As[nb][kq+2][r0]=va0.z; As[nb][kq+3][r0]=va0.w;
            As[nb][kq+0][r0+64]=va1.x; As[nb][kq+1][r0+64]=va1.y; As[nb][kq+2][r0+64]=va1.z; As[nb][kq+3][r0+64]=va1.w;
            *(float4*)&Bs[nb][kr0  ][nq] = vb0;
            *(float4*)&Bs[nb][kr0+8][nq] = vb1;
            __syncthreads();
            buf = nb;
        }
    }

    float bv_[8];
    if (bias){
        float4 t0 = ld4(bias + blockIdx.x*128 + n0);
        float4 t1 = ld4(bias + blockIdx.x*128 + n0 + 4);
        bv_[0]=t0.x*biasScale; bv_[1]=t0.y*biasScale; bv_[2]=t0.z*biasScale; bv_[3]=t0.w*biasScale;
        bv_[4]=t1.x*biasScale; bv_[5]=t1.y*biasScale; bv_[6]=t1.z*biasScale; bv_[7]=t1.w*biasScale;
    } else {
        #pragma unroll
        for (int j=0;j<8;j++) bv_[j]=0.f;
    }

    float* Cb = Cout + (size_t)blockIdx.y*128*CD + blockIdx.x*128;
    const float* Rb = res ? (res + (size_t)blockIdx.y*128*CD + blockIdx.x*128) : nullptr;
    #pragma unroll
    for (int i=0;i<8;i++){
        float o[8];
        #pragma unroll
        for (int j=0;j<8;j++){
            float t = acc[i][j] + bv_[j];
            if (doRelu) t = fmaxf(t, 0.f);
            o[j] = t;
        }
        if (Rb){
            float4 q0 = ld4(Rb + (size_t)(m0+i)*CD + n0);
            float4 q1 = ld4(Rb + (size_t)(m0+i)*CD + n0 + 4);
            o[0]+=q0.x; o[1]+=q0.y; o[2]+=q0.z; o[3]+=q0.w;
            o[4]+=q1.x; o[5]+=q1.y; o[6]+=q1.z; o[7]+=q1.w;
        }
        *(float4*)&Cb[(size_t)(m0+i)*CD + n0  ] = make_float4(o[0],o[1],o[2],o[3]);
        *(float4*)&Cb[(size_t)(m0+i)*CD + n0+4] = make_float4(o[4],o[5],o[6],o[7]);
    }
}

// ================= launch =================
extern "C" void kernel_launch(void* const* d_in, const int* in_sizes, int n_in,
                              void* d_out, int out_size)
{
    const float* x   = (const float*)d_in[0];
    const float* W1m = (const float*)d_in[1];
    const float* b1m = (const float*)d_in[2];
    const float* W2m = (const float*)d_in[3];
    const float* b2m = (const float*)d_in[4];
    const float* W1u = (const float*)d_in[5];
    const float* b1u = (const float*)d_in[6];
    const float* W2u = (const float*)d_in[7];
    const float* b2u = (const float*)d_in[8];
    float* out = (float*)d_out;

    float *p_Am=nullptr, *p_Bm=nullptr, *p_R=nullptr, *p_hagg=nullptr, *p_H=nullptr;
    cudaGetSymbolAddress((void**)&p_Am,   g_Am);
    cudaGetSymbolAddress((void**)&p_Bm,   g_Bm);
    cudaGetSymbolAddress((void**)&p_R,    g_R);
    cudaGetSymbolAddress((void**)&p_hagg, g_hagg);
    cudaGetSymbolAddress((void**)&p_H,    g_H);

    const int SIM_SMEM = 4 * TILE * (int)sizeof(float);   // 73728 B
    cudaFuncSetAttribute(sim_mma_kernel, cudaFuncAttributeMaxDynamicSharedMemorySize, SIM_SMEM);

    rownorm_split_kernel<<<NPTS, 256>>>(x);

    // A_msg = x @ W1_msg[0:256] + b1_msg ; B_msg = x @ W1_msg[256:512]
    mlp_gemm_kernel<<<dim3(2,128), 256>>>(x, nullptr, W1m,          16, b1m, 1.f, 0, nullptr, p_Am);
    mlp_gemm_kernel<<<dim3(2,128), 256>>>(x, nullptr, W1m + 256*CD, 16, nullptr, 0.f, 0, nullptr, p_Bm);

    // sim + topk in row chunks
    for (int cb = 0; cb < NCHUNK; cb++){
        sim_mma_kernel<<<dim3(NPTS/128, CHUNK/128), 256, SIM_SMEM>>>(cb*CHUNK);
        topk_kernel  <<<CHUNK, 256>>>(cb*CHUNK);
    }

    // R_i = sum_j relu(A_i + B_j)
    gather_relu_sum_kernel<<<NPTS, 256>>>();

    // h_agg = R @ W2_msg + 20*b2_msg
    mlp_gemm_kernel<<<dim3(2,128), 256>>>(p_R, nullptr, W2m, 16, b2m, (float)TOPK, 0, nullptr, p_hagg);

    // H = relu(x @ W1u[0:256] + h_agg @ W1u[256:512] + b1u)
    mlp_gemm_kernel<<<dim3(2,128), 256>>>(x, p_hagg, W1u, 32, b1u, 1.f, 1, nullptr, p_H);

    // out = x + H @ W2_upd + b2_upd
    mlp_gemm_kernel<<<dim3(2,128), 256>>>(p_H, nullptr, W2u, 16, b2u, 1.f, 0, x, out);
}

// round 8
// speedup vs baseline: 1.5843x; 1.1411x over previous
#include <cuda_runtime.h>
#include <math.h>
#include <stdint.h>

#define NPTS 16384
#define CD   256
#define KHL  512          // hi|lo concatenated K
#define TOPK 20
#define CAND 32
#define CHUNK 2048
#define NCHUNK (NPTS/CHUNK)
#define CBUF 512

#define SROW 36           // padded smem row stride (floats)
#define TILE (128*SROW)

// -------- scratch (static __device__, no allocations) --------
__device__ float g_xn  [(size_t)NPTS*CD];         // fp32 normalized rows (exact rescore)
__device__ float g_hl  [(size_t)NPTS*KHL];        // [:,0:256]=hi tf32, [:,256:512]=lo tf32
__device__ float g_sim [2][(size_t)CHUNK*NPTS];   // double-buffered 2x128 MB
__device__ float g_bmax[2][(size_t)CHUNK*128];    // per-row per-128col-block max
__device__ int   g_idx [NPTS*TOPK];
__device__ float g_Am  [NPTS*CD];
__device__ float g_Bm  [NPTS*CD];
__device__ float g_R   [NPTS*CD];
__device__ float g_hagg[NPTS*CD];
__device__ float g_H   [NPTS*CD];

static __device__ __forceinline__ float4 ld4(const float* p){
    return *reinterpret_cast<const float4*>(p);
}

// ================= row normalize + tf32 split (hi | lo) =================
__global__ __launch_bounds__(256) void rownorm_split_kernel(const float* __restrict__ x){
    int i = blockIdx.x;
    int t = threadIdx.x;
    float v = x[i*CD + t];
    float s = v*v;
    #pragma unroll
    for (int off=16; off; off>>=1) s += __shfl_xor_sync(0xffffffffu, s, off);
    __shared__ float red[8];
    if ((t & 31) == 0) red[t>>5] = s;
    __syncthreads();
    float tot = red[0]+red[1]+red[2]+red[3]+red[4]+red[5]+red[6]+red[7];
    float rn = 1.0f / fmaxf(sqrtf(tot), 1e-8f);
    float xn = v * rn;
    g_xn[(size_t)i*CD + t] = xn;
    uint32_t hb, lb;
    asm("cvt.rna.tf32.f32 %0, %1;" : "=r"(hb) : "f"(xn));
    float hi = __uint_as_float(hb);
    float lo = xn - hi;
    asm("cvt.rna.tf32.f32 %0, %1;" : "=r"(lb) : "f"(lo));
    g_hl[(size_t)i*KHL + t]       = hi;
    g_hl[(size_t)i*KHL + 256 + t] = __uint_as_float(lb);
}

// ================= sim via mma.sync tf32, K=512 (proven shape) =======
__global__ __launch_bounds__(256,2) void sim_mma_kernel(int rowBase, int bufIdx)
{
    extern __shared__ float smem[];
    float* As = smem;              // [2][128][SROW]
    float* Bs = smem + 2*TILE;     // [2][128][SROW]

    const int tid  = threadIdx.x;
    const int warp = tid >> 5, lane = tid & 31;
    const int wr   = warp >> 1;          // 0..3 (m)
    const int wc   = warp & 1;           // 0..1 (n)
    const int g    = lane >> 2;          // 0..7
    const int tg   = lane & 3;           // 0..3

    const size_t rowA0 = (size_t)rowBase + (size_t)blockIdx.y * 128;
    const size_t rowB0 = (size_t)blockIdx.x * 128;
    const float* __restrict__ gA = g_hl + rowA0 * KHL;
    const float* __restrict__ gB = g_hl + rowB0 * KHL;

    float acc[2][8][4];
    #pragma unroll
    for (int mi=0;mi<2;mi++)
        #pragma unroll
        for (int nj=0;nj<8;nj++)
            #pragma unroll
            for (int q=0;q<4;q++) acc[mi][nj][q]=0.f;

    const int fr[4] = { (tid + 0)   >> 3, (tid + 256) >> 3, (tid + 512) >> 3, (tid + 768) >> 3 };
    const int fc = (tid & 7) * 4;

    #pragma unroll
    for (int p=0;p<4;p++){
        *(float4*)&As[fr[p]*SROW + fc] = ld4(gA + (size_t)fr[p]*KHL + fc);
        *(float4*)&Bs[fr[p]*SROW + fc] = ld4(gB + (size_t)fr[p]*KHL + fc);
    }
    __syncthreads();

    int buf = 0;
    #pragma unroll 1
    for (int kc = 0; kc < 16; kc++){
        float4 va[4], vb[4];
        if (kc < 15){
            const int ko = (kc+1)*32 + fc;
            #pragma unroll
            for (int p=0;p<4;p++){
                va[p] = ld4(gA + (size_t)fr[p]*KHL + ko);
                vb[p] = ld4(gB + (size_t)fr[p]*KHL + ko);
            }
        }

        const float* Ab = &As[buf*TILE + (wr*32)*SROW];
        const float* Bb = &Bs[buf*TILE + (wc*64)*SROW];
        #pragma unroll
        for (int k8=0;k8<4;k8++){
            const int kb = k8*8;
            uint32_t a[2][4];
            #pragma unroll
            for (int mi=0;mi<2;mi++){
                const float* ap = Ab + (mi*16)*SROW + kb;
                a[mi][0] = __float_as_uint(ap[(g  )*SROW + tg  ]);
                a[mi][1] = __float_as_uint(ap[(g+8)*SROW + tg  ]);
                a[mi][2] = __float_as_uint(ap[(g  )*SROW + tg+4]);
                a[mi][3] = __float_as_uint(ap[(g+8)*SROW + tg+4]);
            }
            #pragma unroll
            for (int nj=0;nj<8;nj++){
                const float* bp = Bb + (nj*8)*SROW + kb;
                uint32_t b0 = __float_as_uint(bp[g*SROW + tg  ]);
                uint32_t b1 = __float_as_uint(bp[g*SROW + tg+4]);
                #pragma unroll
                for (int mi=0;mi<2;mi++){
                    asm volatile(
                        "mma.sync.aligned.m16n8k8.row.col.f32.tf32.tf32.f32 "
                        "{%0,%1,%2,%3}, {%4,%5,%6,%7}, {%8,%9}, {%0,%1,%2,%3};"
                        : "+f"(acc[mi][nj][0]), "+f"(acc[mi][nj][1]),
                          "+f"(acc[mi][nj][2]), "+f"(acc[mi][nj][3])
                        : "r"(a[mi][0]), "r"(a[mi][1]), "r"(a[mi][2]), "r"(a[mi][3]),
                          "r"(b0), "r"(b1));
                }
            }
        }

        if (kc < 15){
            const int nb = buf ^ 1;
            #pragma unroll
            for (int p=0;p<4;p++){
                *(float4*)&As[nb*TILE + fr[p]*SROW + fc] = va[p];
                *(float4*)&Bs[nb*TILE + fr[p]*SROW + fc] = vb[p];
            }
            __syncthreads();
            buf = nb;
        }
    }

    // ---- store C ----
    float* simBuf = g_sim[bufIdx];
    float* C = simBuf + ((size_t)blockIdx.y*128 + wr*32 + g) * NPTS
                      + rowB0 + wc*64 + 2*tg;
    #pragma unroll
    for (int mi=0;mi<2;mi++){
        #pragma unroll
        for (int nj=0;nj<8;nj++){
            float* c0 = C + (size_t)(mi*16)*NPTS + nj*8;
            *(float2*)c0                     = make_float2(acc[mi][nj][0], acc[mi][nj][1]);
            *(float2*)(c0 + (size_t)8*NPTS)  = make_float2(acc[mi][nj][2], acc[mi][nj][3]);
        }
    }

    // ---- per-row 128-col-block max -> g_bmax ----
    __syncthreads();                 // smem buffers no longer needed; reuse
    float* sb = smem;                // [128][2]
    #pragma unroll
    for (int mi=0;mi<2;mi++){
        float r0 = -1e30f, r1 = -1e30f;
        #pragma unroll
        for (int nj=0;nj<8;nj++){
            r0 = fmaxf(r0, fmaxf(acc[mi][nj][0], acc[mi][nj][1]));
            r1 = fmaxf(r1, fmaxf(acc[mi][nj][2], acc[mi][nj][3]));
        }
        #pragma unroll
        for (int off=1; off<4; off<<=1){
            r0 = fmaxf(r0, __shfl_xor_sync(0xffffffffu, r0, off));
            r1 = fmaxf(r1, __shfl_xor_sync(0xffffffffu, r1, off));
        }
        if (tg == 0){
            sb[(wr*32 + mi*16 + g  )*2 + wc] = r0;
            sb[(wr*32 + mi*16 + g+8)*2 + wc] = r1;
        }
    }
    __syncthreads();
    if (tid < 128){
        float bm = fmaxf(sb[tid*2], sb[tid*2+1]);
        g_bmax[bufIdx][(size_t)(blockIdx.y*128 + tid)*128 + blockIdx.x] = bm;
    }
}

// ================= top-20: block-max filter + exact fp32 rescore =================
__global__ __launch_bounds__(256) void topk_kernel(int rowBase, int bufIdx)
{
    const int row  = blockIdx.x;           // chunk-local
    const int rowG = rowBase + row;
    const float* __restrict__ S  = g_sim[bufIdx]  + (size_t)row * NPTS;
    const float* __restrict__ BM = g_bmax[bufIdx] + (size_t)row * 128;
    const int tid = threadIdx.x;
    const int lane = tid & 31, warp = tid >> 5;

    __shared__ float s_tau;
    __shared__ int   s_cnt, s_bcnt;
    __shared__ int   blist[128];
    __shared__ float cv[CBUF];
    __shared__ int   ci[CBUF];
    __shared__ float xi[CD];

    xi[tid] = g_xn[(size_t)rowG*CD + tid];
    if (tid == 0){ s_cnt = 0; s_bcnt = 0; }
    __syncthreads();

    // tau = CAND-th largest of the 128 block maxima (valid top-CAND filter)
    if (warp == 0){
        float a[4];
        #pragma unroll
        for (int j=0;j<4;j++) a[j] = BM[lane*4 + j];
        #define CSW(i,j) { if (a[i] < a[j]) { float t=a[i]; a[i]=a[j]; a[j]=t; } }
        CSW(0,1) CSW(2,3) CSW(0,2) CSW(1,3) CSW(1,2)
        #undef CSW
        float tau = -1e30f;
        for (int sel = 0; sel < CAND; sel++){
            float h = a[0];
            float bv = h;
            #pragma unroll
            for (int off=16; off; off>>=1)
                bv = fmaxf(bv, __shfl_xor_sync(0xffffffffu, bv, off));
            unsigned ball = __ballot_sync(0xffffffffu, h == bv);
            if (lane == (__ffs(ball) - 1)){
                #pragma unroll
                for (int j=0;j<3;j++) a[j] = a[j+1];
                a[3] = -1e30f;
            }
            tau = bv;
        }
        if (lane == 0) s_tau = tau;
    }
    __syncthreads();
    const float tau = s_tau;

    // qualifying block list
    if (tid < 128){
        if (BM[tid] >= tau){ int p = atomicAdd(&s_bcnt, 1); blist[p] = tid; }
    }
    __syncthreads();
    const int bcnt = s_bcnt;

    // collect candidates: one warp per qualifying block, float4 per lane
    for (int i = warp; i < bcnt; i += 8){
        const int b = blist[i];
        float4 v = *(const float4*)(S + b*128 + lane*4);
        int base = b*128 + lane*4;
        if (v.x >= tau){ int p = atomicAdd(&s_cnt,1); if (p < CBUF) ci[p] = base+0; }
        if (v.y >= tau){ int p = atomicAdd(&s_cnt,1); if (p < CBUF) ci[p] = base+1; }
        if (v.z >= tau){ int p = atomicAdd(&s_cnt,1); if (p < CBUF) ci[p] = base+2; }
        if (v.w >= tau){ int p = atomicAdd(&s_cnt,1); if (p < CBUF) ci[p] = base+3; }
    }
    __syncthreads();
    int cnt = s_cnt < CBUF ? s_cnt : CBUF;

    // exact fp32 rescore (serial k-ascending fmaf — matches reference selections)
    for (int p = tid; p < cnt; p += 256){
        const float* __restrict__ xj = g_xn + (size_t)ci[p]*CD;
        float acc = 0.f;
        #pragma unroll 8
        for (int k = 0; k < CD; k++)
            acc = fmaf(xi[k], xj[k], acc);
        cv[p] = acc;
    }
    __syncthreads();

    // warp 0 selects top-20 by exact values (tie-break: lowest index)
    if (warp == 0){
        for (int sel = 0; sel < TOPK; sel++){
            float bv = -1e30f; int bi = 0x7fffffff; int bp = -1;
            for (int p = lane; p < cnt; p += 32){
                float vv = cv[p]; int ii = ci[p];
                if (vv > bv || (vv == bv && ii < bi)){ bv = vv; bi = ii; bp = p; }
            }
            #pragma unroll
            for (int off=16; off; off>>=1){
                float ov = __shfl_xor_sync(0xffffffffu, bv, off);
                int   oi = __shfl_xor_sync(0xffffffffu, bi, off);
                int   op = __shfl_xor_sync(0xffffffffu, bp, off);
                if (ov > bv || (ov == bv && oi < bi)){ bv = ov; bi = oi; bp = op; }
            }
            if (lane == 0){
                g_idx[(size_t)rowG*TOPK + sel] = bi;
                cv[bp] = -1e30f;
            }
            __syncwarp();
        }
    }
}

// ================= gather + relu + sum over 20 neighbors =================
__global__ __launch_bounds__(256) void gather_relu_sum_kernel(){
    const int i = blockIdx.x, c = threadIdx.x;
    __shared__ int nb[TOPK];
    if (c < TOPK) nb[c] = g_idx[(size_t)i*TOPK + c];
    __syncthreads();
    float a = g_Am[(size_t)i*CD + c];
    float acc = 0.f;
    #pragma unroll
    for (int k=0;k<TOPK;k++)
        acc += fmaxf(a + g_Bm[(size_t)nb[k]*CD + c], 0.f);
    g_R[(size_t)i*CD + c] = acc;
}

// ================= generic MLP GEMM =================
__global__ __launch_bounds__(256,2) void mlp_gemm_kernel(
    const float* __restrict__ A1, const float* __restrict__ A2,
    const float* __restrict__ W, int nslab,
    const float* __restrict__ bias, float biasScale,
    int doRelu, const float* __restrict__ res,
    float* __restrict__ Cout)
{
    __shared__ float As[2][16][132];
    __shared__ float Bs[2][16][132];
    const int tid = threadIdx.x;
    const int r0 = tid >> 2, kq = (tid & 3) << 2;
    const int kr0 = tid >> 5, nq = (tid & 31) << 2;
    const int tx = tid & 15, ty = tid >> 4;
    const int m0 = tx*8, n0 = ty*8;

    const size_t rowOff = (size_t)blockIdx.y*128*CD;
    const float* A1b = A1 + rowOff;
    const float* A2b = A2 ? (A2 + rowOff) : A1b;
    const float* Wb  = W + blockIdx.x*128;

    float acc[8][8];
    #pragma unroll
    for (int i=0;i<8;i++)
        #pragma unroll
        for (int j=0;j<8;j++) acc[i][j]=0.f;

    float4 va0 = ld4(A1b + r0*CD + kq);
    float4 va1 = ld4(A1b + (r0+64)*CD + kq);
    float4 vb0 = ld4(Wb + (size_t)kr0*CD + nq);
    float4 vb1 = ld4(Wb + (size_t)(kr0+8)*CD + nq);

    As[0][kq+0][r0]=va0.x; As[0][kq+1][r0]=va0.y; As[0][kq+2][r0]=va0.z; As[0][kq+3][r0]=va0.w;
    As[0][kq+0][r0+64]=va1.x; As[0][kq+1][r0+64]=va1.y; As[0][kq+2][r0+64]=va1.z; As[0][kq+3][r0+64]=va1.w;
    *(float4*)&Bs[0][kr0  ][nq] = vb0;
    *(float4*)&Bs[0][kr0+8][nq] = vb1;
    __syncthreads();

    int buf = 0;
    for (int s=0; s<nslab; s++){
        if (s+1 < nslab){
            int kk = (s+1)*16;
            const float* Ag = (kk < 256) ? (A1b + kk) : (A2b + (kk-256));
            va0 = ld4(Ag + r0*CD + kq);
            va1 = ld4(Ag + (r0+64)*CD + kq);
            vb0 = ld4(Wb + (size_t)(kk+kr0)*CD + nq);
            vb1 = ld4(Wb + (size_t)(kk+kr0+8)*CD + nq);
        }
        #pragma unroll
        for (int k=0;k<16;k++){
            float4 a0 = *(const float4*)&As[buf][k][m0];
            float4 a1 = *(const float4*)&As[buf][k][m0+4];
            float4 b0 = *(const float4*)&Bs[buf][k][n0];
            float4 b1 = *(const float4*)&Bs[buf][k][n0+4];
            float av[8] = {a0.x,a0.y,a0.z,a0.w,a1.x,a1.y,a1.z,a1.w};
            float bw[8] = {b0.x,b0.y,b0.z,b0.w,b1.x,b1.y,b1.z,b1.w};
            #pragma unroll
            for (int i=0;i<8;i++)
                #pragma unroll
                for (int j=0;j<8;j++)
                    acc[i][j] = fmaf(av[i], bw[j], acc[i][j]);
        }
        if (s+1 < nslab){
            int nb = buf ^ 1;
            As[nb][kq+0][r0]=va0.x; As[nb][kq+1][r0]=va0.y; As[nb][kq+2][r0]=va0.z; As[nb][kq+3][r0]=va0.w;
            As[nb][kq+0][r0+64]=va1.x; As[nb][kq+1][r0+64]=va1.y; As[nb][kq+2][r0+64]=va1.z; As[nb][kq+3][r0+64]=va1.w;
            *(float4*)&Bs[nb][kr0  ][nq] = vb0;
            *(float4*)&Bs[nb][kr0+8][nq] = vb1;
            __syncthreads();
            buf = nb;
        }
    }

    float bv_[8];
    if (bias){
        float4 t0 = ld4(bias + blockIdx.x*128 + n0);
        float4 t1 = ld4(bias + blockIdx.x*128 + n0 + 4);
        bv_[0]=t0.x*biasScale; bv_[1]=t0.y*biasScale; bv_[2]=t0.z*biasScale; bv_[3]=t0.w*biasScale;
        bv_[4]=t1.x*biasScale; bv_[5]=t1.y*biasScale; bv_[6]=t1.z*biasScale; bv_[7]=t1.w*biasScale;
    } else {
        #pragma unroll
        for (int j=0;j<8;j++) bv_[j]=0.f;
    }

    float* Cb = Cout + (size_t)blockIdx.y*128*CD + blockIdx.x*128;
    const float* Rb = res ? (res + (size_t)blockIdx.y*128*CD + blockIdx.x*128) : nullptr;
    #pragma unroll
    for (int i=0;i<8;i++){
        float o[8];
        #pragma unroll
        for (int j=0;j<8;j++){
            float t = acc[i][j] + bv_[j];
            if (doRelu) t = fmaxf(t, 0.f);
            o[j] = t;
        }
        if (Rb){
            float4 q0 = ld4(Rb + (size_t)(m0+i)*CD + n0);
            float4 q1 = ld4(Rb + (size_t)(m0+i)*CD + n0 + 4);
            o[0]+=q0.x; o[1]+=q0.y; o[2]+=q0.z; o[3]+=q0.w;
            o[4]+=q1.x; o[5]+=q1.y; o[6]+=q1.z; o[7]+=q1.w;
        }
        *(float4*)&Cb[(size_t)(m0+i)*CD + n0  ] = make_float4(o[0],o[1],o[2],o[3]);
        *(float4*)&Cb[(size_t)(m0+i)*CD + n0+4] = make_float4(o[4],o[5],o[6],o[7]);
    }
}

// ================= launch =================
extern "C" void kernel_launch(void* const* d_in, const int* in_sizes, int n_in,
                              void* d_out, int out_size)
{
    const float* x   = (const float*)d_in[0];
    const float* W1m = (const float*)d_in[1];
    const float* b1m = (const float*)d_in[2];
    const float* W2m = (const float*)d_in[3];
    const float* b2m = (const float*)d_in[4];
    const float* W1u = (const float*)d_in[5];
    const float* b1u = (const float*)d_in[6];
    const float* W2u = (const float*)d_in[7];
    const float* b2u = (const float*)d_in[8];
    float* out = (float*)d_out;

    float *p_Am=nullptr, *p_Bm=nullptr, *p_R=nullptr, *p_hagg=nullptr, *p_H=nullptr;
    cudaGetSymbolAddress((void**)&p_Am,   g_Am);
    cudaGetSymbolAddress((void**)&p_Bm,   g_Bm);
    cudaGetSymbolAddress((void**)&p_R,    g_R);
    cudaGetSymbolAddress((void**)&p_hagg, g_hagg);
    cudaGetSymbolAddress((void**)&p_H,    g_H);

    // lazy one-time stream/event creation (host objects only; no device memory)
    static cudaStream_t s2 = nullptr;
    static cudaEvent_t evSim[NCHUNK], evTk[NCHUNK], evFork;
    if (!s2){
        cudaStreamCreateWithFlags(&s2, cudaStreamNonBlocking);
        cudaEventCreateWithFlags(&evFork, cudaEventDisableTiming);
        for (int i = 0; i < NCHUNK; i++){
            cudaEventCreateWithFlags(&evSim[i], cudaEventDisableTiming);
            cudaEventCreateWithFlags(&evTk[i],  cudaEventDisableTiming);
        }
    }

    const int SIM_SMEM = 4 * TILE * (int)sizeof(float);   // 73728 B
    cudaFuncSetAttribute(sim_mma_kernel, cudaFuncAttributeMaxDynamicSharedMemorySize, SIM_SMEM);

    cudaStream_t st = 0;   // capture/default stream

    rownorm_split_kernel<<<NPTS, 256, 0, st>>>(x);

    // A_msg = x @ W1_msg[0:256] + b1_msg ; B_msg = x @ W1_msg[256:512]
    mlp_gemm_kernel<<<dim3(2,128), 256, 0, st>>>(x, nullptr, W1m,          16, b1m, 1.f, 0, nullptr, p_Am);
    mlp_gemm_kernel<<<dim3(2,128), 256, 0, st>>>(x, nullptr, W1m + 256*CD, 16, nullptr, 0.f, 0, nullptr, p_Bm);

    // fork s2 into the capture graph
    cudaEventRecord(evFork, st);
    cudaStreamWaitEvent(s2, evFork, 0);

    // pipelined sim (st) + topk (s2) with double-buffered g_sim
    for (int cb = 0; cb < NCHUNK; cb++){
        const int bi = cb & 1;
        if (cb >= 2) cudaStreamWaitEvent(st, evTk[cb-2], 0);   // buffer reuse guard
        sim_mma_kernel<<<dim3(NPTS/128, CHUNK/128), 256, SIM_SMEM, st>>>(cb*CHUNK, bi);
        cudaEventRecord(evSim[cb], st);
        cudaStreamWaitEvent(s2, evSim[cb], 0);
        topk_kernel<<<CHUNK, 256, 0, s2>>>(cb*CHUNK, bi);
        cudaEventRecord(evTk[cb], s2);
    }
    // join s2 back into st
    cudaStreamWaitEvent(st, evTk[NCHUNK-1], 0);
    cudaStreamWaitEvent(st, evTk[NCHUNK-2], 0);

    // R_i = sum_j relu(A_i + B_j)
    gather_relu_sum_kernel<<<NPTS, 256, 0, st>>>();

    // h_agg = R @ W2_msg + 20*b2_msg
    mlp_gemm_kernel<<<dim3(2,128), 256, 0, st>>>(p_R, nullptr, W2m, 16, b2m, (float)TOPK, 0, nullptr, p_hagg);

    // H = relu(x @ W1u[0:256] + h_agg @ W1u[256:512] + b1u)
    mlp_gemm_kernel<<<dim3(2,128), 256, 0, st>>>(x, p_hagg, W1u, 32, b1u, 1.f, 1, nullptr, p_H);

    // out = x + H @ W2_upd + b2_upd
    mlp_gemm_kernel<<<dim3(2,128), 256, 0, st>>>(p_H, nullptr, W2u, 16, b2u, 1.f, 0, x, out);
}

// round 9
// speedup vs baseline: 2.2300x; 1.4075x over previous
#include <cuda_runtime.h>
#include <math.h>
#include <stdint.h>

#define NPTS 16384
#define CD   256
#define KHL  512          // hi|lo concatenated K
#define TOPK 20
#define CAND 32
#define CHUNK 2048
#define NCHUNK (NPTS/CHUNK)
#define CBUF 512

#define SROW 36           // padded smem row stride (floats)
#define TILE (128*SROW)
#define TSTRIDE 133       // transpose staging stride

// -------- scratch (static __device__, no allocations) --------
__device__ float g_xn  [(size_t)NPTS*CD];         // fp32 normalized rows (exact rescore)
__device__ float g_hl  [(size_t)NPTS*KHL];        // [:,0:256]=hi tf32, [:,256:512]=lo tf32
__device__ float g_sim [(size_t)NPTS*NPTS];       // full 1 GB similarity
__device__ float g_bmax[(size_t)NPTS*128];        // per-row per-128col-block max
__device__ int   g_idx [NPTS*TOPK];
__device__ float g_Am  [NPTS*CD];
__device__ float g_Bm  [NPTS*CD];
__device__ float g_R   [NPTS*CD];
__device__ float g_hagg[NPTS*CD];
__device__ float g_H   [NPTS*CD];

static __device__ __forceinline__ float4 ld4(const float* p){
    return *reinterpret_cast<const float4*>(p);
}

// ================= row normalize + tf32 split (hi | lo) =================
__global__ __launch_bounds__(256) void rownorm_split_kernel(const float* __restrict__ x){
    int i = blockIdx.x;
    int t = threadIdx.x;
    float v = x[i*CD + t];
    float s = v*v;
    #pragma unroll
    for (int off=16; off; off>>=1) s += __shfl_xor_sync(0xffffffffu, s, off);
    __shared__ float red[8];
    if ((t & 31) == 0) red[t>>5] = s;
    __syncthreads();
    float tot = red[0]+red[1]+red[2]+red[3]+red[4]+red[5]+red[6]+red[7];
    float rn = 1.0f / fmaxf(sqrtf(tot), 1e-8f);
    float xn = v * rn;
    g_xn[(size_t)i*CD + t] = xn;
    uint32_t hb, lb;
    asm("cvt.rna.tf32.f32 %0, %1;" : "=r"(hb) : "f"(xn));
    float hi = __uint_as_float(hb);
    float lo = xn - hi;
    asm("cvt.rna.tf32.f32 %0, %1;" : "=r"(lb) : "f"(lo));
    g_hl[(size_t)i*KHL + t]       = hi;
    g_hl[(size_t)i*KHL + 256 + t] = __uint_as_float(lb);
}

// ================= symmetric sim via mma.sync tf32, K=512 =================
// Tile (I,J), J>=I only. Off-diagonal tiles also write the transposed tile.
__global__ __launch_bounds__(256,2) void sim_mma_kernel(int cBase)
{
    if (blockIdx.x < blockIdx.y) return;   // J < I: mirror handled by (J,I) tile
    const int I = cBase + blockIdx.y;
    const int J = cBase + blockIdx.x;

    extern __shared__ float smem[];
    float* As = smem;              // [2][128][SROW]
    float* Bs = smem + 2*TILE;     // [2][128][SROW]

    const int tid  = threadIdx.x;
    const int warp = tid >> 5, lane = tid & 31;
    const int wr   = warp >> 1;          // 0..3 (m)
    const int wc   = warp & 1;           // 0..1 (n)
    const int g    = lane >> 2;          // 0..7
    const int tg   = lane & 3;           // 0..3

    const float* __restrict__ gA = g_hl + (size_t)I * 128 * KHL;
    const float* __restrict__ gB = g_hl + (size_t)J * 128 * KHL;

    float acc[2][8][4];
    #pragma unroll
    for (int mi=0;mi<2;mi++)
        #pragma unroll
        for (int nj=0;nj<8;nj++)
            #pragma unroll
            for (int q=0;q<4;q++) acc[mi][nj][q]=0.f;

    const int fr[4] = { (tid + 0)   >> 3, (tid + 256) >> 3, (tid + 512) >> 3, (tid + 768) >> 3 };
    const int fc = (tid & 7) * 4;

    #pragma unroll
    for (int p=0;p<4;p++){
        *(float4*)&As[fr[p]*SROW + fc] = ld4(gA + (size_t)fr[p]*KHL + fc);
        *(float4*)&Bs[fr[p]*SROW + fc] = ld4(gB + (size_t)fr[p]*KHL + fc);
    }
    __syncthreads();

    int buf = 0;
    #pragma unroll 1
    for (int kc = 0; kc < 16; kc++){
        float4 va[4], vb[4];
        if (kc < 15){
            const int ko = (kc+1)*32 + fc;
            #pragma unroll
            for (int p=0;p<4;p++){
                va[p] = ld4(gA + (size_t)fr[p]*KHL + ko);
                vb[p] = ld4(gB + (size_t)fr[p]*KHL + ko);
            }
        }

        const float* Ab = &As[buf*TILE + (wr*32)*SROW];
        const float* Bb = &Bs[buf*TILE + (wc*64)*SROW];
        #pragma unroll
        for (int k8=0;k8<4;k8++){
            const int kb = k8*8;
            uint32_t a[2][4];
            #pragma unroll
            for (int mi=0;mi<2;mi++){
                const float* ap = Ab + (mi*16)*SROW + kb;
                a[mi][0] = __float_as_uint(ap[(g  )*SROW + tg  ]);
                a[mi][1] = __float_as_uint(ap[(g+8)*SROW + tg  ]);
                a[mi][2] = __float_as_uint(ap[(g  )*SROW + tg+4]);
                a[mi][3] = __float_as_uint(ap[(g+8)*SROW + tg+4]);
            }
            #pragma unroll
            for (int nj=0;nj<8;nj++){
                const float* bp = Bb + (nj*8)*SROW + kb;
                uint32_t b0 = __float_as_uint(bp[g*SROW + tg  ]);
                uint32_t b1 = __float_as_uint(bp[g*SROW + tg+4]);
                #pragma unroll
                for (int mi=0;mi<2;mi++){
                    asm volatile(
                        "mma.sync.aligned.m16n8k8.row.col.f32.tf32.tf32.f32 "
                        "{%0,%1,%2,%3}, {%4,%5,%6,%7}, {%8,%9}, {%0,%1,%2,%3};"
                        : "+f"(acc[mi][nj][0]), "+f"(acc[mi][nj][1]),
                          "+f"(acc[mi][nj][2]), "+f"(acc[mi][nj][3])
                        : "r"(a[mi][0]), "r"(a[mi][1]), "r"(a[mi][2]), "r"(a[mi][3]),
                          "r"(b0), "r"(b1));
                }
            }
        }

        if (kc < 15){
            const int nb = buf ^ 1;
            #pragma unroll
            for (int p=0;p<4;p++){
                *(float4*)&As[nb*TILE + fr[p]*SROW + fc] = va[p];
                *(float4*)&Bs[nb*TILE + fr[p]*SROW + fc] = vb[p];
            }
            __syncthreads();
            buf = nb;
        }
    }

    // ================= epilogue =================
    __syncthreads();                        // done with As/Bs: reuse smem
    float* s  = smem;                       // [128][TSTRIDE] transpose staging
    float* sb = smem + 128*TSTRIDE;         // [128][2] row-max staging

    // direct store + stage into s + per-row partial maxima
    {
        float* C = g_sim + ((size_t)I*128 + wr*32 + g) * NPTS
                         + (size_t)J*128 + wc*64 + 2*tg;
        #pragma unroll
        for (int mi=0;mi<2;mi++){
            #pragma unroll
            for (int nj=0;nj<8;nj++){
                float* c0 = C + (size_t)(mi*16)*NPTS + nj*8;
                *(float2*)c0                     = make_float2(acc[mi][nj][0], acc[mi][nj][1]);
                *(float2*)(c0 + (size_t)8*NPTS)  = make_float2(acc[mi][nj][2], acc[mi][nj][3]);
                const int r0 = wr*32 + mi*16 + g;
                const int c0i = wc*64 + nj*8 + 2*tg;
                s[(r0  )*TSTRIDE + c0i  ] = acc[mi][nj][0];
                s[(r0  )*TSTRIDE + c0i+1] = acc[mi][nj][1];
                s[(r0+8)*TSTRIDE + c0i  ] = acc[mi][nj][2];
                s[(r0+8)*TSTRIDE + c0i+1] = acc[mi][nj][3];
            }
        }
    }

    // direct per-row tile max via shuffles
    #pragma unroll
    for (int mi=0;mi<2;mi++){
        float r0 = -1e30f, r1 = -1e30f;
        #pragma unroll
        for (int nj=0;nj<8;nj++){
            r0 = fmaxf(r0, fmaxf(acc[mi][nj][0], acc[mi][nj][1]));
            r1 = fmaxf(r1, fmaxf(acc[mi][nj][2], acc[mi][nj][3]));
        }
        #pragma unroll
        for (int off=1; off<4; off<<=1){
            r0 = fmaxf(r0, __shfl_xor_sync(0xffffffffu, r0, off));
            r1 = fmaxf(r1, __shfl_xor_sync(0xffffffffu, r1, off));
        }
        if (tg == 0){
            sb[(wr*32 + mi*16 + g  )*2 + wc] = r0;
            sb[(wr*32 + mi*16 + g+8)*2 + wc] = r1;
        }
    }
    __syncthreads();
    if (tid < 128){
        float bm = fmaxf(sb[tid*2], sb[tid*2+1]);
        g_bmax[(size_t)(I*128 + tid)*128 + J] = bm;
    }

    // transposed tile (J,I) for off-diagonal
    if (I != J){
        const int rp = tid >> 1;               // 0..127: CT row
        const int cb = (tid & 1) * 64;         // column half
        float* CT = g_sim + (size_t)(J*128 + rp) * NPTS + (size_t)I*128 + cb;
        float mx = -1e30f;
        #pragma unroll
        for (int k = 0; k < 16; k++){
            const int c = cb + 4*k;
            float4 v = make_float4(
                s[(c  )*TSTRIDE + rp], s[(c+1)*TSTRIDE + rp],
                s[(c+2)*TSTRIDE + rp], s[(c+3)*TSTRIDE + rp]);
            *(float4*)(CT + 4*k) = v;
            mx = fmaxf(mx, fmaxf(fmaxf(v.x, v.y), fmaxf(v.z, v.w)));
        }
        float o = __shfl_xor_sync(0xffffffffu, mx, 1);
        mx = fmaxf(mx, o);
        if ((tid & 1) == 0)
            g_bmax[(size_t)(J*128 + rp)*128 + I] = mx;
    }
}

// ================= top-20: block-max filter + exact fp32 rescore =================
__global__ __launch_bounds__(256) void topk_kernel(int rowBase)
{
    const int rowG = rowBase + blockIdx.x;
    const float* __restrict__ S  = g_sim  + (size_t)rowG * NPTS;
    const float* __restrict__ BM = g_bmax + (size_t)rowG * 128;
    const int tid = threadIdx.x;
    const int lane = tid & 31, warp = tid >> 5;

    __shared__ float s_tau;
    __shared__ int   s_cnt, s_bcnt;
    __shared__ int   blist[128];
    __shared__ float cv[CBUF];
    __shared__ int   ci[CBUF];
    __shared__ float xi[CD];

    xi[tid] = g_xn[(size_t)rowG*CD + tid];
    if (tid == 0){ s_cnt = 0; s_bcnt = 0; }
    __syncthreads();

    // tau = CAND-th largest of the 128 block maxima (valid top-CAND filter)
    if (warp == 0){
        float a[4];
        #pragma unroll
        for (int j=0;j<4;j++) a[j] = BM[lane*4 + j];
        #define CSW(i,j) { if (a[i] < a[j]) { float t=a[i]; a[i]=a[j]; a[j]=t; } }
        CSW(0,1) CSW(2,3) CSW(0,2) CSW(1,3) CSW(1,2)
        #undef CSW
        float tau = -1e30f;
        for (int sel = 0; sel < CAND; sel++){
            float h = a[0];
            float bv = h;
            #pragma unroll
            for (int off=16; off; off>>=1)
                bv = fmaxf(bv, __shfl_xor_sync(0xffffffffu, bv, off));
            unsigned ball = __ballot_sync(0xffffffffu, h == bv);
            if (lane == (__ffs(ball) - 1)){
                #pragma unroll
                for (int j=0;j<3;j++) a[j] = a[j+1];
                a[3] = -1e30f;
            }
            tau = bv;
        }
        if (lane == 0) s_tau = tau;
    }
    __syncthreads();
    const float tau = s_tau;

    if (tid < 128){
        if (BM[tid] >= tau){ int p = atomicAdd(&s_bcnt, 1); blist[p] = tid; }
    }
    __syncthreads();
    const int bcnt = s_bcnt;

    // collect candidates: one warp per qualifying block, float4 per lane
    for (int i = warp; i < bcnt; i += 8){
        const int b = blist[i];
        float4 v = *(const float4*)(S + b*128 + lane*4);
        int base = b*128 + lane*4;
        if (v.x >= tau){ int p = atomicAdd(&s_cnt,1); if (p < CBUF) ci[p] = base+0; }
        if (v.y >= tau){ int p = atomicAdd(&s_cnt,1); if (p < CBUF) ci[p] = base+1; }
        if (v.z >= tau){ int p = atomicAdd(&s_cnt,1); if (p < CBUF) ci[p] = base+2; }
        if (v.w >= tau){ int p = atomicAdd(&s_cnt,1); if (p < CBUF) ci[p] = base+3; }
    }
    __syncthreads();
    int cnt = s_cnt < CBUF ? s_cnt : CBUF;

    // exact fp32 rescore (serial k-ascending fmaf — matches reference selections)
    for (int p = tid; p < cnt; p += 256){
        const float* __restrict__ xj = g_xn + (size_t)ci[p]*CD;
        float acc = 0.f;
        #pragma unroll 8
        for (int k = 0; k < CD; k++)
            acc = fmaf(xi[k], xj[k], acc);
        cv[p] = acc;
    }
    __syncthreads();

    // warp 0 selects top-20 by exact values (tie-break: lowest index)
    if (warp == 0){
        for (int sel = 0; sel < TOPK; sel++){
            float bv = -1e30f; int bi = 0x7fffffff; int bp = -1;
            for (int p = lane; p < cnt; p += 32){
                float vv = cv[p]; int ii = ci[p];
                if (vv > bv || (vv == bv && ii < bi)){ bv = vv; bi = ii; bp = p; }
            }
            #pragma unroll
            for (int off=16; off; off>>=1){
                float ov = __shfl_xor_sync(0xffffffffu, bv, off);
                int   oi = __shfl_xor_sync(0xffffffffu, bi, off);
                int   op = __shfl_xor_sync(0xffffffffu, bp, off);
                if (ov > bv || (ov == bv && oi < bi)){ bv = ov; bi = oi; bp = op; }
            }
            if (lane == 0){
                g_idx[(size_t)rowG*TOPK + sel] = bi;
                cv[bp] = -1e30f;
            }
            __syncwarp();
        }
    }
}

// ================= gather + relu + sum over 20 neighbors =================
__global__ __launch_bounds__(256) void gather_relu_sum_kernel(){
    const int i = blockIdx.x, c = threadIdx.x;
    __shared__ int nb[TOPK];
    if (c < TOPK) nb[c] = g_idx[(size_t)i*TOPK + c];
    __syncthreads();
    float a = g_Am[(size_t)i*CD + c];
    float acc = 0.f;
    #pragma unroll
    for (int k=0;k<TOPK;k++)
        acc += fmaxf(a + g_Bm[(size_t)nb[k]*CD + c], 0.f);
    g_R[(size_t)i*CD + c] = acc;
}

// ================= generic MLP GEMM =================
__global__ __launch_bounds__(256,2) void mlp_gemm_kernel(
    const float* __restrict__ A1, const float* __restrict__ A2,
    const float* __restrict__ W, int nslab,
    const float* __restrict__ bias, float biasScale,
    int doRelu, const float* __restrict__ res,
    float* __restrict__ Cout)
{
    __shared__ float As[2][16][132];
    __shared__ float Bs[2][16][132];
    const int tid = threadIdx.x;
    const int r0 = tid >> 2, kq = (tid & 3) << 2;
    const int kr0 = tid >> 5, nq = (tid & 31) << 2;
    const int tx = tid & 15, ty = tid >> 4;
    const int m0 = tx*8, n0 = ty*8;

    const size_t rowOff = (size_t)blockIdx.y*128*CD;
    const float* A1b = A1 + rowOff;
    const float* A2b = A2 ? (A2 + rowOff) : A1b;
    const float* Wb  = W + blockIdx.x*128;

    float acc[8][8];
    #pragma unroll
    for (int i=0;i<8;i++)
        #pragma unroll
        for (int j=0;j<8;j++) acc[i][j]=0.f;

    float4 va0 = ld4(A1b + r0*CD + kq);
    float4 va1 = ld4(A1b + (r0+64)*CD + kq);
    float4 vb0 = ld4(Wb + (size_t)kr0*CD + nq);
    float4 vb1 = ld4(Wb + (size_t)(kr0+8)*CD + nq);

    As[0][kq+0][r0]=va0.x; As[0][kq+1][r0]=va0.y; As[0][kq+2][r0]=va0.z; As[0][kq+3][r0]=va0.w;
    As[0][kq+0][r0+64]=va1.x; As[0][kq+1][r0+64]=va1.y; As[0][kq+2][r0+64]=va1.z; As[0][kq+3][r0+64]=va1.w;
    *(float4*)&Bs[0][kr0  ][nq] = vb0;
    *(float4*)&Bs[0][kr0+8][nq] = vb1;
    __syncthreads();

    int buf = 0;
    for (int s=0; s<nslab; s++){
        if (s+1 < nslab){
            int kk = (s+1)*16;
            const float* Ag = (kk < 256) ? (A1b + kk) : (A2b + (kk-256));
            va0 = ld4(Ag + r0*CD + kq);
            va1 = ld4(Ag + (r0+64)*CD + kq);
            vb0 = ld4(Wb + (size_t)(kk+kr0)*CD + nq);
            vb1 = ld4(Wb + (size_t)(kk+kr0+8)*CD + nq);
        }
        #pragma unroll
        for (int k=0;k<16;k++){
            float4 a0 = *(const float4*)&As[buf][k][m0];
            float4 a1 = *(const float4*)&As[buf][k][m0+4];
            float4 b0 = *(const float4*)&Bs[buf][k][n0];
            float4 b1 = *(const float4*)&Bs[buf][k][n0+4];
            float av[8] = {a0.x,a0.y,a0.z,a0.w,a1.x,a1.y,a1.z,a1.w};
            float bw[8] = {b0.x,b0.y,b0.z,b0.w,b1.x,b1.y,b1.z,b1.w};
            #pragma unroll
            for (int i=0;i<8;i++)
                #pragma unroll
                for (int j=0;j<8;j++)
                    acc[i][j] = fmaf(av[i], bw[j], acc[i][j]);
        }
        if (s+1 < nslab){
            int nb = buf ^ 1;
            As[nb][kq+0][r0]=va0.x; As[nb][kq+1][r0]=va0.y; As[nb][kq+2][r0]=va0.z; As[nb][kq+3][r0]=va0.w;
            As[nb][kq+0][r0+64]=va1.x; As[nb][kq+1][r0+64]=va1.y; As[nb][kq+2][r0+64]=va1.z; As[nb][kq+3][r0+64]=va1.w;
            *(float4*)&Bs[nb][kr0  ][nq] = vb0;
            *(float4*)&Bs[nb][kr0+8][nq] = vb1;
            __syncthreads();
            buf = nb;
        }
    }

    float bv_[8];
    if (bias){
        float4 t0 = ld4(bias + blockIdx.x*128 + n0);
        float4 t1 = ld4(bias + blockIdx.x*128 + n0 + 4);
        bv_[0]=t0.x*biasScale; bv_[1]=t0.y*biasScale; bv_[2]=t0.z*biasScale; bv_[3]=t0.w*biasScale;
        bv_[4]=t1.x*biasScale; bv_[5]=t1.y*biasScale; bv_[6]=t1.z*biasScale; bv_[7]=t1.w*biasScale;
    } else {
        #pragma unroll
        for (int j=0;j<8;j++) bv_[j]=0.f;
    }

    float* Cb = Cout + (size_t)blockIdx.y*128*CD + blockIdx.x*128;
    const float* Rb = res ? (res + (size_t)blockIdx.y*128*CD + blockIdx.x*128) : nullptr;
    #pragma unroll
    for (int i=0;i<8;i++){
        float o[8];
        #pragma unroll
        for (int j=0;j<8;j++){
            float t = acc[i][j] + bv_[j];
            if (doRelu) t = fmaxf(t, 0.f);
            o[j] = t;
        }
        if (Rb){
            float4 q0 = ld4(Rb + (size_t)(m0+i)*CD + n0);
            float4 q1 = ld4(Rb + (size_t)(m0+i)*CD + n0 + 4);
            o[0]+=q0.x; o[1]+=q0.y; o[2]+=q0.z; o[3]+=q0.w;
            o[4]+=q1.x; o[5]+=q1.y; o[6]+=q1.z; o[7]+=q1.w;
        }
        *(float4*)&Cb[(size_t)(m0+i)*CD + n0  ] = make_float4(o[0],o[1],o[2],o[3]);
        *(float4*)&Cb[(size_t)(m0+i)*CD + n0+4] = make_float4(o[4],o[5],o[6],o[7]);
    }
}

// ================= launch =================
extern "C" void kernel_launch(void* const* d_in, const int* in_sizes, int n_in,
                              void* d_out, int out_size)
{
    const float* x   = (const float*)d_in[0];
    const float* W1m = (const float*)d_in[1];
    const float* b1m = (const float*)d_in[2];
    const float* W2m = (const float*)d_in[3];
    const float* b2m = (const float*)d_in[4];
    const float* W1u = (const float*)d_in[5];
    const float* b1u = (const float*)d_in[6];
    const float* W2u = (const float*)d_in[7];
    const float* b2u = (const float*)d_in[8];
    float* out = (float*)d_out;

    float *p_Am=nullptr, *p_Bm=nullptr, *p_R=nullptr, *p_hagg=nullptr, *p_H=nullptr;
    cudaGetSymbolAddress((void**)&p_Am,   g_Am);
    cudaGetSymbolAddress((void**)&p_Bm,   g_Bm);
    cudaGetSymbolAddress((void**)&p_R,    g_R);
    cudaGetSymbolAddress((void**)&p_hagg, g_hagg);
    cudaGetSymbolAddress((void**)&p_H,    g_H);

    static cudaStream_t s2 = nullptr;
    static cudaEvent_t evSim[NCHUNK], evTk[NCHUNK], evFork;
    if (!s2){
        cudaStreamCreateWithFlags(&s2, cudaStreamNonBlocking);
        cudaEventCreateWithFlags(&evFork, cudaEventDisableTiming);
        for (int i = 0; i < NCHUNK; i++){
            cudaEventCreateWithFlags(&evSim[i], cudaEventDisableTiming);
            cudaEventCreateWithFlags(&evTk[i],  cudaEventDisableTiming);
        }
    }

    const int SIM_SMEM = 4 * TILE * (int)sizeof(float);   // 73728 B
    cudaFuncSetAttribute(sim_mma_kernel, cudaFuncAttributeMaxDynamicSharedMemorySize, SIM_SMEM);

    cudaStream_t st = 0;

    rownorm_split_kernel<<<NPTS, 256, 0, st>>>(x);

    // fork s2
    cudaEventRecord(evFork, st);
    cudaStreamWaitEvent(s2, evFork, 0);

    // A_msg / B_msg on s2 (overlap with sim)
    mlp_gemm_kernel<<<dim3(2,128), 256, 0, s2>>>(x, nullptr, W1m,          16, b1m, 1.f, 0, nullptr, p_Am);
    mlp_gemm_kernel<<<dim3(2,128), 256, 0, s2>>>(x, nullptr, W1m + 256*CD, 16, nullptr, 0.f, 0, nullptr, p_Bm);

    // band-ordered symmetric sim (st) + per-band topk (s2)
    for (int c = 0; c < NCHUNK; c++){
        const int cBase = c * 16;                 // tile-row offset (128-row tiles)
        const int gw = 128 - cBase;               // J range width
        sim_mma_kernel<<<dim3(gw, 16), 256, SIM_SMEM, st>>>(cBase);
        cudaEventRecord(evSim[c], st);
        cudaStreamWaitEvent(s2, evSim[c], 0);
        topk_kernel<<<CHUNK, 256, 0, s2>>>(c*CHUNK);
        cudaEventRecord(evTk[c], s2);
    }
    cudaStreamWaitEvent(st, evTk[NCHUNK-1], 0);

    // R_i = sum_j relu(A_i + B_j)
    gather_relu_sum_kernel<<<NPTS, 256, 0, st>>>();

    // h_agg = R @ W2_msg + 20*b2_msg
    mlp_gemm_kernel<<<dim3(2,128), 256, 0, st>>>(p_R, nullptr, W2m, 16, b2m, (float)TOPK, 0, nullptr, p_hagg);

    // H = relu(x @ W1u[0:256] + h_agg @ W1u[256:512] + b1u)
    mlp_gemm_kernel<<<dim3(2,128), 256, 0, st>>>(x, p_hagg, W1u, 32, b1u, 1.f, 1, nullptr, p_H);

    // out = x + H @ W2_upd + b2_upd
    mlp_gemm_kernel<<<dim3(2,128), 256, 0, st>>>(p_H, nullptr, W2u, 16, b2u, 1.f, 0, x, out);
}

// round 10
// speedup vs baseline: 2.6539x; 1.1901x over previous
#include <cuda_runtime.h>
#include <cuda_bf16.h>
#include <math.h>
#include <stdint.h>

#define NPTS 16384
#define CD   256
#define KHL  512          // hi|lo concatenated K (bf16 elements)
#define TOPK 20
#define CAND 32
#define CHUNK 2048
#define NCHUNK (NPTS/CHUNK)
#define CBUF 512

#define BSROW 72          // smem row stride in bf16 (144 B = 36 words: conflict-free)
#define BTILE (128*BSROW) // bf16 elements per operand tile
#define TSTRIDE 133       // transpose staging stride (floats)

// -------- scratch (static __device__, no allocations) --------
__device__ float          g_xn [(size_t)NPTS*CD];   // fp32 normalized rows (exact rescore)
__device__ __nv_bfloat16  g_hb [(size_t)NPTS*KHL];  // [:,0:256]=hi bf16, [:,256:512]=lo bf16
__device__ float g_sim [(size_t)NPTS*NPTS];         // full 1 GB similarity
__device__ float g_bmax[(size_t)NPTS*128];          // per-row per-128col-block max
__device__ int   g_idx [NPTS*TOPK];
__device__ float g_Am  [NPTS*CD];
__device__ float g_Bm  [NPTS*CD];
__device__ float g_R   [NPTS*CD];
__device__ float g_hagg[NPTS*CD];
__device__ float g_H   [NPTS*CD];

static __device__ __forceinline__ float4 ld4(const float* p){
    return *reinterpret_cast<const float4*>(p);
}

// ================= row normalize + bf16 2-split (hi | lo) =================
__global__ __launch_bounds__(256) void rownorm_split_kernel(const float* __restrict__ x){
    int i = blockIdx.x;
    int t = threadIdx.x;
    float v = x[i*CD + t];
    float s = v*v;
    #pragma unroll
    for (int off=16; off; off>>=1) s += __shfl_xor_sync(0xffffffffu, s, off);
    __shared__ float red[8];
    if ((t & 31) == 0) red[t>>5] = s;
    __syncthreads();
    float tot = red[0]+red[1]+red[2]+red[3]+red[4]+red[5]+red[6]+red[7];
    float rn = 1.0f / fmaxf(sqrtf(tot), 1e-8f);
    float xn = v * rn;
    g_xn[(size_t)i*CD + t] = xn;
    __nv_bfloat16 h = __float2bfloat16(xn);
    float hf = __bfloat162float(h);
    __nv_bfloat16 l = __float2bfloat16(xn - hf);
    g_hb[(size_t)i*KHL + t]       = h;
    g_hb[(size_t)i*KHL + 256 + t] = l;
}

// ================= symmetric sim via mma.sync bf16, K=512 =================
// Tile (I,J), J>=I only. Off-diagonal tiles also write the transposed tile.
__global__ __launch_bounds__(256,2) void sim_mma_kernel(int cBase)
{
    if (blockIdx.x < blockIdx.y) return;   // J < I: mirror handled by (J,I) tile
    const int I = cBase + blockIdx.y;
    const int J = cBase + blockIdx.x;

    extern __shared__ float smem[];
    __nv_bfloat16* smb = reinterpret_cast<__nv_bfloat16*>(smem);
    // layout: [buf][ A: BTILE | B: BTILE ] bf16

    const int tid  = threadIdx.x;
    const int warp = tid >> 5, lane = tid & 31;
    const int wr   = warp >> 1;          // 0..3 (m)
    const int wc   = warp & 1;           // 0..1 (n)
    const int g    = lane >> 2;          // 0..7
    const int tg   = lane & 3;           // 0..3

    const __nv_bfloat16* __restrict__ gA = g_hb + (size_t)I * 128 * KHL;
    const __nv_bfloat16* __restrict__ gB = g_hb + (size_t)J * 128 * KHL;

    float acc[2][8][4];
    #pragma unroll
    for (int mi=0;mi<2;mi++)
        #pragma unroll
        for (int nj=0;nj<8;nj++)
            #pragma unroll
            for (int q=0;q<4;q++) acc[mi][nj][q]=0.f;

    const int fr[4] = { (tid + 0)   >> 3, (tid + 256) >> 3, (tid + 512) >> 3, (tid + 768) >> 3 };
    const int col8 = (tid & 7) * 8;      // bf16 column offset (16B granularity)

    // prologue: fill buf 0 for kc=0 (each kc = 64 bf16 per row = 128 B)
    #pragma unroll
    for (int p=0;p<4;p++){
        *(float4*)&smb[fr[p]*BSROW + col8]         = ld4((const float*)(gA + (size_t)fr[p]*KHL + col8));
        *(float4*)&smb[BTILE + fr[p]*BSROW + col8] = ld4((const float*)(gB + (size_t)fr[p]*KHL + col8));
    }
    __syncthreads();

    int buf = 0;
    #pragma unroll 1
    for (int kc = 0; kc < 8; kc++){
        float4 va[4], vb[4];
        if (kc < 7){
            const int ko = (kc+1)*64 + col8;
            #pragma unroll
            for (int p=0;p<4;p++){
                va[p] = ld4((const float*)(gA + (size_t)fr[p]*KHL + ko));
                vb[p] = ld4((const float*)(gB + (size_t)fr[p]*KHL + ko));
            }
        }

        const __nv_bfloat16* Ab = smb + buf*2*BTILE + (wr*32)*BSROW;
        const __nv_bfloat16* Bb = smb + buf*2*BTILE + BTILE + (wc*64)*BSROW;
        #pragma unroll
        for (int ks=0;ks<4;ks++){
            const int kb = ks*16;            // bf16 k offset within chunk
            uint32_t a[2][4];
            #pragma unroll
            for (int mi=0;mi<2;mi++){
                const __nv_bfloat16* ap = Ab + (mi*16)*BSROW + kb;
                a[mi][0] = *(const uint32_t*)&ap[(g  )*BSROW + 2*tg    ];
                a[mi][1] = *(const uint32_t*)&ap[(g+8)*BSROW + 2*tg    ];
                a[mi][2] = *(const uint32_t*)&ap[(g  )*BSROW + 2*tg + 8];
                a[mi][3] = *(const uint32_t*)&ap[(g+8)*BSROW + 2*tg + 8];
            }
            #pragma unroll
            for (int nj=0;nj<8;nj++){
                const __nv_bfloat16* bp = Bb + (nj*8)*BSROW + kb;
                uint32_t b0 = *(const uint32_t*)&bp[g*BSROW + 2*tg    ];
                uint32_t b1 = *(const uint32_t*)&bp[g*BSROW + 2*tg + 8];
                #pragma unroll
                for (int mi=0;mi<2;mi++){
                    asm volatile(
                        "mma.sync.aligned.m16n8k16.row.col.f32.bf16.bf16.f32 "
                        "{%0,%1,%2,%3}, {%4,%5,%6,%7}, {%8,%9}, {%0,%1,%2,%3};"
                        : "+f"(acc[mi][nj][0]), "+f"(acc[mi][nj][1]),
                          "+f"(acc[mi][nj][2]), "+f"(acc[mi][nj][3])
                        : "r"(a[mi][0]), "r"(a[mi][1]), "r"(a[mi][2]), "r"(a[mi][3]),
                          "r"(b0), "r"(b1));
                }
            }
        }

        if (kc < 7){
            const int nb = buf ^ 1;
            #pragma unroll
            for (int p=0;p<4;p++){
                *(float4*)&smb[nb*2*BTILE + fr[p]*BSROW + col8]         = va[p];
                *(float4*)&smb[nb*2*BTILE + BTILE + fr[p]*BSROW + col8] = vb[p];
            }
            __syncthreads();
            buf = nb;
        }
    }

    // ================= epilogue =================
    __syncthreads();                        // done with operand tiles: reuse smem
    float* s  = smem;                       // [128][TSTRIDE] transpose staging
    float* sb = smem + 128*TSTRIDE;         // [128][2] row-max staging

    // direct store + stage into s
    {
        float* C = g_sim + ((size_t)I*128 + wr*32 + g) * NPTS
                         + (size_t)J*128 + wc*64 + 2*tg;
        #pragma unroll
        for (int mi=0;mi<2;mi++){
            #pragma unroll
            for (int nj=0;nj<8;nj++){
                float* c0 = C + (size_t)(mi*16)*NPTS + nj*8;
                *(float2*)c0                     = make_float2(acc[mi][nj][0], acc[mi][nj][1]);
                *(float2*)(c0 + (size_t)8*NPTS)  = make_float2(acc[mi][nj][2], acc[mi][nj][3]);
                const int r0 = wr*32 + mi*16 + g;
                const int c0i = wc*64 + nj*8 + 2*tg;
                s[(r0  )*TSTRIDE + c0i  ] = acc[mi][nj][0];
                s[(r0  )*TSTRIDE + c0i+1] = acc[mi][nj][1];
                s[(r0+8)*TSTRIDE + c0i  ] = acc[mi][nj][2];
                s[(r0+8)*TSTRIDE + c0i+1] = acc[mi][nj][3];
            }
        }
    }

    // direct per-row tile max via shuffles
    #pragma unroll
    for (int mi=0;mi<2;mi++){
        float r0 = -1e30f, r1 = -1e30f;
        #pragma unroll
        for (int nj=0;nj<8;nj++){
            r0 = fmaxf(r0, fmaxf(acc[mi][nj][0], acc[mi][nj][1]));
            r1 = fmaxf(r1, fmaxf(acc[mi][nj][2], acc[mi][nj][3]));
        }
        #pragma unroll
        for (int off=1; off<4; off<<=1){
            r0 = fmaxf(r0, __shfl_xor_sync(0xffffffffu, r0, off));
            r1 = fmaxf(r1, __shfl_xor_sync(0xffffffffu, r1, off));
        }
        if (tg == 0){
            sb[(wr*32 + mi*16 + g  )*2 + wc] = r0;
            sb[(wr*32 + mi*16 + g+8)*2 + wc] = r1;
        }
    }
    __syncthreads();
    if (tid < 128){
        float bm = fmaxf(sb[tid*2], sb[tid*2+1]);
        g_bmax[(size_t)(I*128 + tid)*128 + J] = bm;
    }

    // transposed tile (J,I) for off-diagonal
    if (I != J){
        const int rp = tid >> 1;               // 0..127: CT row
        const int cb = (tid & 1) * 64;         // column half
        float* CT = g_sim + (size_t)(J*128 + rp) * NPTS + (size_t)I*128 + cb;
        float mx = -1e30f;
        #pragma unroll
        for (int k = 0; k < 16; k++){
            const int c = cb + 4*k;
            float4 v = make_float4(
                s[(c  )*TSTRIDE + rp], s[(c+1)*TSTRIDE + rp],
                s[(c+2)*TSTRIDE + rp], s[(c+3)*TSTRIDE + rp]);
            *(float4*)(CT + 4*k) = v;
            mx = fmaxf(mx, fmaxf(fmaxf(v.x, v.y), fmaxf(v.z, v.w)));
        }
        float o = __shfl_xor_sync(0xffffffffu, mx, 1);
        mx = fmaxf(mx, o);
        if ((tid & 1) == 0)
            g_bmax[(size_t)(J*128 + rp)*128 + I] = mx;
    }
}

// ================= top-20: block-max filter + exact fp32 rescore =================
__global__ __launch_bounds__(256) void topk_kernel(int rowBase)
{
    const int rowG = rowBase + blockIdx.x;
    const float* __restrict__ S  = g_sim  + (size_t)rowG * NPTS;
    const float* __restrict__ BM = g_bmax + (size_t)rowG * 128;
    const int tid = threadIdx.x;
    const int lane = tid & 31, warp = tid >> 5;

    __shared__ float s_tau;
    __shared__ int   s_cnt, s_bcnt;
    __shared__ int   blist[128];
    __shared__ float cv[CBUF];
    __shared__ int   ci[CBUF];
    __shared__ float xi[CD];

    xi[tid] = g_xn[(size_t)rowG*CD + tid];
    if (tid == 0){ s_cnt = 0; s_bcnt = 0; }
    __syncthreads();

    // tau = CAND-th largest of the 128 block maxima (valid top-CAND filter)
    if (warp == 0){
        float a[4];
        #pragma unroll
        for (int j=0;j<4;j++) a[j] = BM[lane*4 + j];
        #define CSW(i,j) { if (a[i] < a[j]) { float t=a[i]; a[i]=a[j]; a[j]=t; } }
        CSW(0,1) CSW(2,3) CSW(0,2) CSW(1,3) CSW(1,2)
        #undef CSW
        float tau = -1e30f;
        for (int sel = 0; sel < CAND; sel++){
            float h = a[0];
            float bv = h;
            #pragma unroll
            for (int off=16; off; off>>=1)
                bv = fmaxf(bv, __shfl_xor_sync(0xffffffffu, bv, off));
            unsigned ball = __ballot_sync(0xffffffffu, h == bv);
            if (lane == (__ffs(ball) - 1)){
                #pragma unroll
                for (int j=0;j<3;j++) a[j] = a[j+1];
                a[3] = -1e30f;
            }
            tau = bv;
        }
        if (lane == 0) s_tau = tau;
    }
    __syncthreads();
    const float tau = s_tau;

    if (tid < 128){
        if (BM[tid] >= tau){ int p = atomicAdd(&s_bcnt, 1); blist[p] = tid; }
    }
    __syncthreads();
    const int bcnt = s_bcnt;

    // collect candidates: one warp per qualifying block, float4 per lane
    for (int i = warp; i < bcnt; i += 8){
        const int b = blist[i];
        float4 v = *(const float4*)(S + b*128 + lane*4);
        int base = b*128 + lane*4;
        if (v.x >= tau){ int p = atomicAdd(&s_cnt,1); if (p < CBUF) ci[p] = base+0; }
        if (v.y >= tau){ int p = atomicAdd(&s_cnt,1); if (p < CBUF) ci[p] = base+1; }
        if (v.z >= tau){ int p = atomicAdd(&s_cnt,1); if (p < CBUF) ci[p] = base+2; }
        if (v.w >= tau){ int p = atomicAdd(&s_cnt,1); if (p < CBUF) ci[p] = base+3; }
    }
    __syncthreads();
    int cnt = s_cnt < CBUF ? s_cnt : CBUF;

    // exact fp32 rescore (serial k-ascending fmaf — matches reference selections)
    for (int p = tid; p < cnt; p += 256){
        const float* __restrict__ xj = g_xn + (size_t)ci[p]*CD;
        float acc = 0.f;
        #pragma unroll 8
        for (int k = 0; k < CD; k++)
            acc = fmaf(xi[k], xj[k], acc);
        cv[p] = acc;
    }
    __syncthreads();

    // warp 0 selects top-20 by exact values (tie-break: lowest index)
    if (warp == 0){
        for (int sel = 0; sel < TOPK; sel++){
            float bv = -1e30f; int bi = 0x7fffffff; int bp = -1;
            for (int p = lane; p < cnt; p += 32){
                float vv = cv[p]; int ii = ci[p];
                if (vv > bv || (vv == bv && ii < bi)){ bv = vv; bi = ii; bp = p; }
            }
            #pragma unroll
            for (int off=16; off; off>>=1){
                float ov = __shfl_xor_sync(0xffffffffu, bv, off);
                int   oi = __shfl_xor_sync(0xffffffffu, bi, off);
                int   op = __shfl_xor_sync(0xffffffffu, bp, off);
                if (ov > bv || (ov == bv && oi < bi)){ bv = ov; bi = oi; bp = op; }
            }
            if (lane == 0){
                g_idx[(size_t)rowG*TOPK + sel] = bi;
                cv[bp] = -1e30f;
            }
            __syncwarp();
        }
    }
}

// ================= gather + relu + sum over 20 neighbors =================
__global__ __launch_bounds__(256) void gather_relu_sum_kernel(){
    const int i = blockIdx.x, c = threadIdx.x;
    __shared__ int nb[TOPK];
    if (c < TOPK) nb[c] = g_idx[(size_t)i*TOPK + c];
    __syncthreads();
    float a = g_Am[(size_t)i*CD + c];
    float acc = 0.f;
    #pragma unroll
    for (int k=0;k<TOPK;k++)
        acc += fmaxf(a + g_Bm[(size_t)nb[k]*CD + c], 0.f);
    g_R[(size_t)i*CD + c] = acc;
}

// ================= generic MLP GEMM =================
__global__ __launch_bounds__(256,2) void mlp_gemm_kernel(
    const float* __restrict__ A1, const float* __restrict__ A2,
    const float* __restrict__ W, int nslab,
    const float* __restrict__ bias, float biasScale,
    int doRelu, const float* __restrict__ res,
    float* __restrict__ Cout)
{
    __shared__ float As[2][16][132];
    __shared__ float Bs[2][16][132];
    const int tid = threadIdx.x;
    const int r0 = tid >> 2, kq = (tid & 3) << 2;
    const int kr0 = tid >> 5, nq = (tid & 31) << 2;
    const int tx = tid & 15, ty = tid >> 4;
    const int m0 = tx*8, n0 = ty*8;

    const size_t rowOff = (size_t)blockIdx.y*128*CD;
    const float* A1b = A1 + rowOff;
    const float* A2b = A2 ? (A2 + rowOff) : A1b;
    const float* Wb  = W + blockIdx.x*128;

    float acc[8][8];
    #pragma unroll
    for (int i=0;i<8;i++)
        #pragma unroll
        for (int j=0;j<8;j++) acc[i][j]=0.f;

    float4 va0 = ld4(A1b + r0*CD + kq);
    float4 va1 = ld4(A1b + (r0+64)*CD + kq);
    float4 vb0 = ld4(Wb + (size_t)kr0*CD + nq);
    float4 vb1 = ld4(Wb + (size_t)(kr0+8)*CD + nq);

    As[0][kq+0][r0]=va0.x; As[0][kq+1][r0]=va0.y; As[0][kq+2][r0]=va0.z; As[0][kq+3][r0]=va0.w;
    As[0][kq+0][r0+64]=va1.x; As[0][kq+1][r0+64]=va1.y; As[0][kq+2][r0+64]=va1.z; As[0][kq+3][r0+64]=va1.w;
    *(float4*)&Bs[0][kr0  ][nq] = vb0;
    *(float4*)&Bs[0][kr0+8][nq] = vb1;
    __syncthreads();

    int buf = 0;
    for (int s=0; s<nslab; s++){
        if (s+1 < nslab){
            int kk = (s+1)*16;
            const float* Ag = (kk < 256) ? (A1b + kk) : (A2b + (kk-256));
            va0 = ld4(Ag + r0*CD + kq);
            va1 = ld4(Ag + (r0+64)*CD + kq);
            vb0 = ld4(Wb + (size_t)(kk+kr0)*CD + nq);
            vb1 = ld4(Wb + (size_t)(kk+kr0+8)*CD + nq);
        }
        #pragma unroll
        for (int k=0;k<16;k++){
            float4 a0 = *(const float4*)&As[buf][k][m0];
            float4 a1 = *(const float4*)&As[buf][k][m0+4];
            float4 b0 = *(const float4*)&Bs[buf][k][n0];
            float4 b1 = *(const float4*)&Bs[buf][k][n0+4];
            float av[8] = {a0.x,a0.y,a0.z,a0.w,a1.x,a1.y,a1.z,a1.w};
            float bw[8] = {b0.x,b0.y,b0.z,b0.w,b1.x,b1.y,b1.z,b1.w};
            #pragma unroll
            for (int i=0;i<8;i++)
                #pragma unroll
                for (int j=0;j<8;j++)
                    acc[i][j] = fmaf(av[i], bw[j], acc[i][j]);
        }
        if (s+1 < nslab){
            int nb = buf ^ 1;
            As[nb][kq+0][r0]=va0.x; As[nb][kq+1][r0]=va0.y; As[nb][kq+2][r0]=va0.z; As[nb][kq+3][r0]=va0.w;
            As[nb][kq+0][r0+64]=va1.x; As[nb][kq+1][r0+64]=va1.y; As[nb][kq+2][r0+64]=va1.z; As[nb][kq+3][r0+64]=va1.w;
            *(float4*)&Bs[nb][kr0  ][nq] = vb0;
            *(float4*)&Bs[nb][kr0+8][nq] = vb1;
            __syncthreads();
            buf = nb;
        }
    }

    float bv_[8];
    if (bias){
        float4 t0 = ld4(bias + blockIdx.x*128 + n0);
        float4 t1 = ld4(bias + blockIdx.x*128 + n0 + 4);
        bv_[0]=t0.x*biasScale; bv_[1]=t0.y*biasScale; bv_[2]=t0.z*biasScale; bv_[3]=t0.w*biasScale;
        bv_[4]=t1.x*biasScale; bv_[5]=t1.y*biasScale; bv_[6]=t1.z*biasScale; bv_[7]=t1.w*biasScale;
    } else {
        #pragma unroll
        for (int j=0;j<8;j++) bv_[j]=0.f;
    }

    float* Cb = Cout + (size_t)blockIdx.y*128*CD + blockIdx.x*128;
    const float* Rb = res ? (res + (size_t)blockIdx.y*128*CD + blockIdx.x*128) : nullptr;
    #pragma unroll
    for (int i=0;i<8;i++){
        float o[8];
        #pragma unroll
        for (int j=0;j<8;j++){
            float t = acc[i][j] + bv_[j];
            if (doRelu) t = fmaxf(t, 0.f);
            o[j] = t;
        }
        if (Rb){
            float4 q0 = ld4(Rb + (size_t)(m0+i)*CD + n0);
            float4 q1 = ld4(Rb + (size_t)(m0+i)*CD + n0 + 4);
            o[0]+=q0.x; o[1]+=q0.y; o[2]+=q0.z; o[3]+=q0.w;
            o[4]+=q1.x; o[5]+=q1.y; o[6]+=q1.z; o[7]+=q1.w;
        }
        *(float4*)&Cb[(size_t)(m0+i)*CD + n0  ] = make_float4(o[0],o[1],o[2],o[3]);
        *(float4*)&Cb[(size_t)(m0+i)*CD + n0+4] = make_float4(o[4],o[5],o[6],o[7]);
    }
}

// ================= launch =================
extern "C" void kernel_launch(void* const* d_in, const int* in_sizes, int n_in,
                              void* d_out, int out_size)
{
    const float* x   = (const float*)d_in[0];
    const float* W1m = (const float*)d_in[1];
    const float* b1m = (const float*)d_in[2];
    const float* W2m = (const float*)d_in[3];
    const float* b2m = (const float*)d_in[4];
    const float* W1u = (const float*)d_in[5];
    const float* b1u = (const float*)d_in[6];
    const float* W2u = (const float*)d_in[7];
    const float* b2u = (const float*)d_in[8];
    float* out = (float*)d_out;

    float *p_Am=nullptr, *p_Bm=nullptr, *p_R=nullptr, *p_hagg=nullptr, *p_H=nullptr;
    cudaGetSymbolAddress((void**)&p_Am,   g_Am);
    cudaGetSymbolAddress((void**)&p_Bm,   g_Bm);
    cudaGetSymbolAddress((void**)&p_R,    g_R);
    cudaGetSymbolAddress((void**)&p_hagg, g_hagg);
    cudaGetSymbolAddress((void**)&p_H,    g_H);

    static cudaStream_t s2 = nullptr;
    static cudaEvent_t evSim[NCHUNK], evTk[NCHUNK], evFork;
    if (!s2){
        cudaStreamCreateWithFlags(&s2, cudaStreamNonBlocking);
        cudaEventCreateWithFlags(&evFork, cudaEventDisableTiming);
        for (int i = 0; i < NCHUNK; i++){
            cudaEventCreateWithFlags(&evSim[i], cudaEventDisableTiming);
            cudaEventCreateWithFlags(&evTk[i],  cudaEventDisableTiming);
        }
    }

    // smem: max(operand tiles 2*2*BTILE*2B = 73728, epilogue 128*133*4+1024 = 69120)
    const int SIM_SMEM = 4 * BTILE * (int)sizeof(__nv_bfloat16);   // 73728 B
    cudaFuncSetAttribute(sim_mma_kernel, cudaFuncAttributeMaxDynamicSharedMemorySize, SIM_SMEM);

    cudaStream_t st = 0;

    rownorm_split_kernel<<<NPTS, 256, 0, st>>>(x);

    // fork s2
    cudaEventRecord(evFork, st);
    cudaStreamWaitEvent(s2, evFork, 0);

    // A_msg / B_msg on s2 (overlap with sim)
    mlp_gemm_kernel<<<dim3(2,128), 256, 0, s2>>>(x, nullptr, W1m,          16, b1m, 1.f, 0, nullptr, p_Am);
    mlp_gemm_kernel<<<dim3(2,128), 256, 0, s2>>>(x, nullptr, W1m + 256*CD, 16, nullptr, 0.f, 0, nullptr, p_Bm);

    // band-ordered symmetric sim (st) + per-band topk (s2)
    for (int c = 0; c < NCHUNK; c++){
        const int cBase = c * 16;                 // tile-row offset (128-row tiles)
        const int gw = 128 - cBase;               // J range width
        sim_mma_kernel<<<dim3(gw, 16), 256, SIM_SMEM, st>>>(cBase);
        cudaEventRecord(evSim[c], st);
        cudaStreamWaitEvent(s2, evSim[c], 0);
        topk_kernel<<<CHUNK, 256, 0, s2>>>(c*CHUNK);
        cudaEventRecord(evTk[c], s2);
    }
    cudaStreamWaitEvent(st, evTk[NCHUNK-1], 0);

    // R_i = sum_j relu(A_i + B_j)
    gather_relu_sum_kernel<<<NPTS, 256, 0, st>>>();

    // h_agg = R @ W2_msg + 20*b2_msg
    mlp_gemm_kernel<<<dim3(2,128), 256, 0, st>>>(p_R, nullptr, W2m, 16, b2m, (float)TOPK, 0, nullptr, p_hagg);

    // H = relu(x @ W1u[0:256] + h_agg @ W1u[256:512] + b1u)
    mlp_gemm_kernel<<<dim3(2,128), 256, 0, st>>>(x, p_hagg, W1u, 32, b1u, 1.f, 1, nullptr, p_H);

    // out = x + H @ W2_upd + b2_upd
    mlp_gemm_kernel<<<dim3(2,128), 256, 0, st>>>(p_H, nullptr, W2u, 16, b2u, 1.f, 0, x, out);
}

// round 12
// speedup vs baseline: 2.6624x; 1.0032x over previous
#include <cuda_runtime.h>
#include <cuda_bf16.h>
#include <math.h>
#include <stdint.h>

#define NPTS 16384
#define CD   256
#define KHL  512          // hi|lo concatenated K (bf16 elements)
#define TOPK 20
#define CAND 32
#define CHUNK 2048
#define NCHUNK (NPTS/CHUNK)
#define CBUF 512

#define BSROW 72          // smem row stride in bf16 (144 B: ldmatrix conflict-free)
#define BTILE (128*BSROW) // bf16 elements per operand tile
#define TSTRIDE 133       // transpose staging stride (floats)

// -------- scratch (static __device__, no allocations) --------
__device__ float          g_xn [(size_t)NPTS*CD];   // fp32 normalized rows (exact rescore)
__device__ __nv_bfloat16  g_hb [(size_t)NPTS*KHL];  // [:,0:256]=hi bf16, [:,256:512]=lo bf16
__device__ float g_sim [(size_t)NPTS*NPTS];         // full 1 GB similarity
__device__ float g_bmax[(size_t)NPTS*128];          // per-row per-128col-block max
__device__ int   g_idx [NPTS*TOPK];
__device__ float g_Am  [NPTS*CD];
__device__ float g_Bm  [NPTS*CD];
__device__ float g_R   [NPTS*CD];
__device__ float g_hagg[NPTS*CD];
__device__ float g_H   [NPTS*CD];

static __device__ __forceinline__ float4 ld4(const float* p){
    return *reinterpret_cast<const float4*>(p);
}
static __device__ __forceinline__ uint32_t smem_u32(const void* p){
    uint32_t a;
    asm("{ .reg .u64 t; cvta.to.shared.u64 t, %1; cvt.u32.u64 %0, t; }" : "=r"(a) : "l"(p));
    return a;
}

// ================= row normalize + bf16 2-split (hi | lo) =================
__global__ __launch_bounds__(256) void rownorm_split_kernel(const float* __restrict__ x){
    int i = blockIdx.x;
    int t = threadIdx.x;
    float v = x[i*CD + t];
    float s = v*v;
    #pragma unroll
    for (int off=16; off; off>>=1) s += __shfl_xor_sync(0xffffffffu, s, off);
    __shared__ float red[8];
    if ((t & 31) == 0) red[t>>5] = s;
    __syncthreads();
    float tot = red[0]+red[1]+red[2]+red[3]+red[4]+red[5]+red[6]+red[7];
    float rn = 1.0f / fmaxf(sqrtf(tot), 1e-8f);
    float xn = v * rn;
    g_xn[(size_t)i*CD + t] = xn;
    __nv_bfloat16 h = __float2bfloat16(xn);
    float hf = __bfloat162float(h);
    __nv_bfloat16 l = __float2bfloat16(xn - hf);
    g_hb[(size_t)i*KHL + t]       = h;
    g_hb[(size_t)i*KHL + 256 + t] = l;
}

// ================= symmetric sim via mma.sync bf16 + ldmatrix, K=512 ==========
__global__ __launch_bounds__(256,2) void sim_mma_kernel(int cBase)
{
    if (blockIdx.x < blockIdx.y) return;   // J < I: mirror handled by (J,I) tile
    const int I = cBase + blockIdx.y;
    const int J = cBase + blockIdx.x;

    extern __shared__ float smem[];
    __nv_bfloat16* smb = reinterpret_cast<__nv_bfloat16*>(smem);
    const uint32_t smbase = smem_u32(smb);

    const int tid  = threadIdx.x;
    const int warp = tid >> 5, lane = tid & 31;
    const int wr   = warp >> 1;          // 0..3 (m)
    const int wc   = warp & 1;           // 0..1 (n)
    const int g    = lane >> 2;          // 0..7
    const int tg   = lane & 3;           // 0..3
    const int lrow = lane & 15;          // ldmatrix row
    const int lhalf= (lane >> 4) * 8;    // ldmatrix k-half (bf16 elems)

    const __nv_bfloat16* __restrict__ gA = g_hb + (size_t)I * 128 * KHL;
    const __nv_bfloat16* __restrict__ gB = g_hb + (size_t)J * 128 * KHL;

    float acc[2][8][4];
    #pragma unroll
    for (int mi=0;mi<2;mi++)
        #pragma unroll
        for (int nj=0;nj<8;nj++)
            #pragma unroll
            for (int q=0;q<4;q++) acc[mi][nj][q]=0.f;

    const int fr[4] = { (tid + 0)   >> 3, (tid + 256) >> 3, (tid + 512) >> 3, (tid + 768) >> 3 };
    const int col8 = (tid & 7) * 8;      // bf16 column offset (16B granularity)

    // prologue: fill buf 0 for kc=0 (each kc = 64 bf16 per row = 128 B)
    #pragma unroll
    for (int p=0;p<4;p++){
        *(float4*)&smb[fr[p]*BSROW + col8]         = ld4((const float*)(gA + (size_t)fr[p]*KHL + col8));
        *(float4*)&smb[BTILE + fr[p]*BSROW + col8] = ld4((const float*)(gB + (size_t)fr[p]*KHL + col8));
    }
    __syncthreads();

    int buf = 0;
    #pragma unroll 1
    for (int kc = 0; kc < 8; kc++){
        float4 va[4], vb[4];
        if (kc < 7){
            const int ko = (kc+1)*64 + col8;
            #pragma unroll
            for (int p=0;p<4;p++){
                va[p] = ld4((const float*)(gA + (size_t)fr[p]*KHL + ko));
                vb[p] = ld4((const float*)(gB + (size_t)fr[p]*KHL + ko));
            }
        }

        // smem byte bases for this warp's A/B sub-tiles
        const uint32_t Abase = smbase + (uint32_t)(buf*2*BTILE + (wr*32)*BSROW) * 2u;
        const uint32_t Bbase = smbase + (uint32_t)(buf*2*BTILE + BTILE + (wc*64)*BSROW) * 2u;

        #pragma unroll
        for (int ks=0;ks<4;ks++){
            const int kb = ks*16;            // bf16 k offset within chunk
            uint32_t a[2][4];
            #pragma unroll
            for (int mi=0;mi<2;mi++){
                uint32_t addr = Abase + (uint32_t)(((mi*16 + lrow)*BSROW) + kb + lhalf) * 2u;
                asm volatile(
                    "ldmatrix.sync.aligned.m8n8.x4.shared.b16 {%0,%1,%2,%3}, [%4];"
                    : "=r"(a[mi][0]), "=r"(a[mi][1]), "=r"(a[mi][2]), "=r"(a[mi][3])
                    : "r"(addr));
            }
            uint32_t bfrag[4][4];   // [njp]{nj_even:b0, nj_odd:b0, nj_even:b1, nj_odd:b1}
            #pragma unroll
            for (int njp=0;njp<4;njp++){
                uint32_t addr = Bbase + (uint32_t)(((njp*16 + lrow)*BSROW) + kb + lhalf) * 2u;
                asm volatile(
                    "ldmatrix.sync.aligned.m8n8.x4.shared.b16 {%0,%1,%2,%3}, [%4];"
                    : "=r"(bfrag[njp][0]), "=r"(bfrag[njp][1]),
                      "=r"(bfrag[njp][2]), "=r"(bfrag[njp][3])
                    : "r"(addr));
            }
            #pragma unroll
            for (int nj=0;nj<8;nj++){
                const uint32_t b0 = bfrag[nj>>1][(nj&1)    ];
                const uint32_t b1 = bfrag[nj>>1][(nj&1) + 2];
                #pragma unroll
                for (int mi=0;mi<2;mi++){
                    asm volatile(
                        "mma.sync.aligned.m16n8k16.row.col.f32.bf16.bf16.f32 "
                        "{%0,%1,%2,%3}, {%4,%5,%6,%7}, {%8,%9}, {%0,%1,%2,%3};"
                        : "+f"(acc[mi][nj][0]), "+f"(acc[mi][nj][1]),
                          "+f"(acc[mi][nj][2]), "+f"(acc[mi][nj][3])
                        : "r"(a[mi][0]), "r"(a[mi][1]), "r"(a[mi][2]), "r"(a[mi][3]),
                          "r"(b0), "r"(b1));
                }
            }
        }

        if (kc < 7){
            const int nb = buf ^ 1;
            #pragma unroll
            for (int p=0;p<4;p++){
                *(float4*)&smb[nb*2*BTILE + fr[p]*BSROW + col8]         = va[p];
                *(float4*)&smb[nb*2*BTILE + BTILE + fr[p]*BSROW + col8] = vb[p];
            }
            __syncthreads();
            buf = nb;
        }
    }

    // ================= epilogue =================
    __syncthreads();                        // done with operand tiles: reuse smem
    float* s  = smem;                       // [128][TSTRIDE] transpose staging
    float* sb = smem + 128*TSTRIDE;         // [128][2] row-max staging

    // direct store + stage into s
    {
        float* C = g_sim + ((size_t)I*128 + wr*32 + g) * NPTS
                         + (size_t)J*128 + wc*64 + 2*tg;
        #pragma unroll
        for (int mi=0;mi<2;mi++){
            #pragma unroll
            for (int nj=0;nj<8;nj++){
                float* c0 = C + (size_t)(mi*16)*NPTS + nj*8;
                *(float2*)c0                     = make_float2(acc[mi][nj][0], acc[mi][nj][1]);
                *(float2*)(c0 + (size_t)8*NPTS)  = make_float2(acc[mi][nj][2], acc[mi][nj][3]);
                const int r0 = wr*32 + mi*16 + g;
                const int c0i = wc*64 + nj*8 + 2*tg;
                s[(r0  )*TSTRIDE + c0i  ] = acc[mi][nj][0];
                s[(r0  )*TSTRIDE + c0i+1] = acc[mi][nj][1];
                s[(r0+8)*TSTRIDE + c0i  ] = acc[mi][nj][2];
                s[(r0+8)*TSTRIDE + c0i+1] = acc[mi][nj][3];
            }
        }
    }

    // direct per-row tile max via shuffles
    #pragma unroll
    for (int mi=0;mi<2;mi++){
        float r0 = -1e30f, r1 = -1e30f;
        #pragma unroll
        for (int nj=0;nj<8;nj++){
            r0 = fmaxf(r0, fmaxf(acc[mi][nj][0], acc[mi][nj][1]));
            r1 = fmaxf(r1, fmaxf(acc[mi][nj][2], acc[mi][nj][3]));
        }
        #pragma unroll
        for (int off=1; off<4; off<<=1){
            r0 = fmaxf(r0, __shfl_xor_sync(0xffffffffu, r0, off));
            r1 = fmaxf(r1, __shfl_xor_sync(0xffffffffu, r1, off));
        }
        if (tg == 0){
            sb[(wr*32 + mi*16 + g  )*2 + wc] = r0;
            sb[(wr*32 + mi*16 + g+8)*2 + wc] = r1;
        }
    }
    __syncthreads();
    if (tid < 128){
        float bm = fmaxf(sb[tid*2], sb[tid*2+1]);
        g_bmax[(size_t)(I*128 + tid)*128 + J] = bm;
    }

    // transposed tile (J,I) for off-diagonal
    if (I != J){
        const int rp = tid >> 1;               // 0..127: CT row
        const int cb = (tid & 1) * 64;         // column half
        float* CT = g_sim + (size_t)(J*128 + rp) * NPTS + (size_t)I*128 + cb;
        float mx = -1e30f;
        #pragma unroll
        for (int k = 0; k < 16; k++){
            const int c = cb + 4*k;
            float4 v = make_float4(
                s[(c  )*TSTRIDE + rp], s[(c+1)*TSTRIDE + rp],
                s[(c+2)*TSTRIDE + rp], s[(c+3)*TSTRIDE + rp]);
            *(float4*)(CT + 4*k) = v;
            mx = fmaxf(mx, fmaxf(fmaxf(v.x, v.y), fmaxf(v.z, v.w)));
        }
        float o = __shfl_xor_sync(0xffffffffu, mx, 1);
        mx = fmaxf(mx, o);
        if ((tid & 1) == 0)
            g_bmax[(size_t)(J*128 + rp)*128 + I] = mx;
    }
}

// ================= top-20: block-max filter + exact fp32 rescore =================
__global__ __launch_bounds__(256) void topk_kernel(int rowBase)
{
    const int rowG = rowBase + blockIdx.x;
    const float* __restrict__ S  = g_sim  + (size_t)rowG * NPTS;
    const float* __restrict__ BM = g_bmax + (size_t)rowG * 128;
    const int tid = threadIdx.x;
    const int lane = tid & 31, warp = tid >> 5;

    __shared__ float s_tau;
    __shared__ int   s_cnt, s_bcnt;
    __shared__ int   blist[128];
    __shared__ float cv[CBUF];
    __shared__ int   ci[CBUF];
    __shared__ float xi[CD];

    xi[tid] = g_xn[(size_t)rowG*CD + tid];
    if (tid == 0){ s_cnt = 0; s_bcnt = 0; }
    __syncthreads();

    // tau = CAND-th largest of the 128 block maxima (valid top-CAND filter)
    if (warp == 0){
        float a[4];
        #pragma unroll
        for (int j=0;j<4;j++) a[j] = BM[lane*4 + j];
        #define CSW(i,j) { if (a[i] < a[j]) { float t=a[i]; a[i]=a[j]; a[j]=t; } }
        CSW(0,1) CSW(2,3) CSW(0,2) CSW(1,3) CSW(1,2)
        #undef CSW
        float tau = -1e30f;
        for (int sel = 0; sel < CAND; sel++){
            float h = a[0];
            float bv = h;
            #pragma unroll
            for (int off=16; off; off>>=1)
                bv = fmaxf(bv, __shfl_xor_sync(0xffffffffu, bv, off));
            unsigned ball = __ballot_sync(0xffffffffu, h == bv);
            if (lane == (__ffs(ball) - 1)){
                #pragma unroll
                for (int j=0;j<3;j++) a[j] = a[j+1];
                a[3] = -1e30f;
            }
            tau = bv;
        }
        if (lane == 0) s_tau = tau;
    }
    __syncthreads();
    const float tau = s_tau;

    if (tid < 128){
        if (BM[tid] >= tau){ int p = atomicAdd(&s_bcnt, 1); blist[p] = tid; }
    }
    __syncthreads();
    const int bcnt = s_bcnt;

    // collect candidates: one warp per qualifying block, float4 per lane
    for (int i = warp; i < bcnt; i += 8){
        const int b = blist[i];
        float4 v = *(const float4*)(S + b*128 + lane*4);
        int base = b*128 + lane*4;
        if (v.x >= tau){ int p = atomicAdd(&s_cnt,1); if (p < CBUF) ci[p] = base+0; }
        if (v.y >= tau){ int p = atomicAdd(&s_cnt,1); if (p < CBUF) ci[p] = base+1; }
        if (v.z >= tau){ int p = atomicAdd(&s_cnt,1); if (p < CBUF) ci[p] = base+2; }
        if (v.w >= tau){ int p = atomicAdd(&s_cnt,1); if (p < CBUF) ci[p] = base+3; }
    }
    __syncthreads();
    int cnt = s_cnt < CBUF ? s_cnt : CBUF;

    // exact fp32 rescore (serial k-ascending fmaf — matches reference selections)
    for (int p = tid; p < cnt; p += 256){
        const float* __restrict__ xj = g_xn + (size_t)ci[p]*CD;
        float acc = 0.f;
        #pragma unroll 8
        for (int k = 0; k < CD; k++)
            acc = fmaf(xi[k], xj[k], acc);
        cv[p] = acc;
    }
    __syncthreads();

    // warp 0 selects top-20 by exact values (tie-break: lowest index)
    if (warp == 0){
        for (int sel = 0; sel < TOPK; sel++){
            float bv = -1e30f; int bi = 0x7fffffff; int bp = -1;
            for (int p = lane; p < cnt; p += 32){
                float vv = cv[p]; int ii = ci[p];
                if (vv > bv || (vv == bv && ii < bi)){ bv = vv; bi = ii; bp = p; }
            }
            #pragma unroll
            for (int off=16; off; off>>=1){
                float ov = __shfl_xor_sync(0xffffffffu, bv, off);
                int   oi = __shfl_xor_sync(0xffffffffu, bi, off);
                int   op = __shfl_xor_sync(0xffffffffu, bp, off);
                if (ov > bv || (ov == bv && oi < bi)){ bv = ov; bi = oi; bp = op; }
            }
            if (lane == 0){
                g_idx[(size_t)rowG*TOPK + sel] = bi;
                cv[bp] = -1e30f;
            }
            __syncwarp();
        }
    }
}

// ================= gather + relu + sum over 20 neighbors =================
__global__ __launch_bounds__(256) void gather_relu_sum_kernel(){
    const int i = blockIdx.x, c = threadIdx.x;
    __shared__ int nb[TOPK];
    if (c < TOPK) nb[c] = g_idx[(size_t)i*TOPK + c];
    __syncthreads();
    float a = g_Am[(size_t)i*CD + c];
    float acc = 0.f;
    #pragma unroll
    for (int k=0;k<TOPK;k++)
        acc += fmaxf(a + g_Bm[(size_t)nb[k]*CD + c], 0.f);
    g_R[(size_t)i*CD + c] = acc;
}

// ================= generic MLP GEMM =================
__global__ __launch_bounds__(256,2) void mlp_gemm_kernel(
    const float* __restrict__ A1, const float* __restrict__ A2,
    const float* __restrict__ W, int nslab,
    const float* __restrict__ bias, float biasScale,
    int doRelu, const float* __restrict__ res,
    float* __restrict__ Cout)
{
    __shared__ float As[2][16][132];
    __shared__ float Bs[2][16][132];
    const int tid = threadIdx.x;
    const int r0 = tid >> 2, kq = (tid & 3) << 2;
    const int kr0 = tid >> 5, nq = (tid & 31) << 2;
    const int tx = tid & 15, ty = tid >> 4;
    const int m0 = tx*8, n0 = ty*8;

    const size_t rowOff = (size_t)blockIdx.y*128*CD;
    const float* A1b = A1 + rowOff;
    const float* A2b = A2 ? (A2 + rowOff) : A1b;
    const float* Wb  = W + blockIdx.x*128;

    float acc[8][8];
    #pragma unroll
    for (int i=0;i<8;i++)
        #pragma unroll
        for (int j=0;j<8;j++) acc[i][j]=0.f;

    float4 va0 = ld4(A1b + r0*CD + kq);
    float4 va1 = ld4(A1b + (r0+64)*CD + kq);
    float4 vb0 = ld4(Wb + (size_t)kr0*CD + nq);
    float4 vb1 = ld4(Wb + (size_t)(kr0+8)*CD + nq);

    As[0][kq+0][r0]=va0.x; As[0][kq+1][r0]=va0.y; As[0][kq+2][r0]=va0.z; As[0][kq+3][r0]=va0.w;
    As[0][kq+0][r0+64]=va1.x; As[0][kq+1][r0+64]=va1.y; As[0][kq+2][r0+64]=va1.z; As[0][kq+3][r0+64]=va1.w;
    *(float4*)&Bs[0][kr0  ][nq] = vb0;
    *(float4*)&Bs[0][kr0+8][nq] = vb1;
    __syncthreads();

    int buf = 0;
    for (int s=0; s<nslab; s++){
        if (s+1 < nslab){
            int kk = (s+1)*16;
            const float* Ag = (kk < 256) ? (A1b + kk) : (A2b + (kk-256));
            va0 = ld4(Ag + r0*CD + kq);
            va1 = ld4(Ag + (r0+64)*CD + kq);
            vb0 = ld4(Wb + (size_t)(kk+kr0)*CD + nq);
            vb1 = ld4(Wb + (size_t)(kk+kr0+8)*CD + nq);
        }
        #pragma unroll
        for (int k=0;k<16;k++){
            float4 a0 = *(const float4*)&As[buf][k][m0];
            float4 a1 = *(const float4*)&As[buf][k][m0+4];
            float4 b0 = *(const float4*)&Bs[buf][k][n0];
            float4 b1 = *(const float4*)&Bs[buf][k][n0+4];
            float av[8] = {a0.x,a0.y,a0.z,a0.w,a1.x,a1.y,a1.z,a1.w};
            float bw[8] = {b0.x,b0.y,b0.z,b0.w,b1.x,b1.y,b1.z,b1.w};
            #pragma unroll
            for (int i=0;i<8;i++)
                #pragma unroll
                for (int j=0;j<8;j++)
                    acc[i][j] = fmaf(av[i], bw[j], acc[i][j]);
        }
        if (s+1 < nslab){
            int nb = buf ^ 1;
            As[nb][kq+0][r0]=va0.x; As[nb][kq+1][r0]=va0.y; As[nb][kq+2][r0]=va0.z; As[nb][kq+3][r0]=va0.w;
            As[nb][kq+0][r0+64]=va1.x; As[nb][kq+1][r0+64]=va1.y; As[nb][kq+2][r0+64]=va1.z; As[nb][kq+3][r0+64]=va1.w;
            *(float4*)&Bs[nb][kr0  ][nq] = vb0;
            *(float4*)&Bs[nb][kr0+8][nq] = vb1;
            __syncthreads();
            buf = nb;
        }
    }

    float bv_[8];
    if (bias){
        float4 t0 = ld4(bias + blockIdx.x*128 + n0);
        float4 t1 = ld4(bias + blockIdx.x*128 + n0 + 4);
        bv_[0]=t0.x*biasScale; bv_[1]=t0.y*biasScale; bv_[2]=t0.z*biasScale; bv_[3]=t0.w*biasScale;
        bv_[4]=t1.x*biasScale; bv_[5]=t1.y*biasScale; bv_[6]=t1.z*biasScale; bv_[7]=t1.w*biasScale;
    } else {
        #pragma unroll
        for (int j=0;j<8;j++) bv_[j]=0.f;
    }

    float* Cb = Cout + (size_t)blockIdx.y*128*CD + blockIdx.x*128;
    const float* Rb = res ? (res + (size_t)blockIdx.y*128*CD + blockIdx.x*128) : nullptr;
    #pragma unroll
    for (int i=0;i<8;i++){
        float o[8];
        #pragma unroll
        for (int j=0;j<8;j++){
            float t = acc[i][j] + bv_[j];
            if (doRelu) t = fmaxf(t, 0.f);
            o[j] = t;
        }
        if (Rb){
            float4 q0 = ld4(Rb + (size_t)(m0+i)*CD + n0);
            float4 q1 = ld4(Rb + (size_t)(m0+i)*CD + n0 + 4);
            o[0]+=q0.x; o[1]+=q0.y; o[2]+=q0.z; o[3]+=q0.w;
            o[4]+=q1.x; o[5]+=q1.y; o[6]+=q1.z; o[7]+=q1.w;
        }
        *(float4*)&Cb[(size_t)(m0+i)*CD + n0  ] = make_float4(o[0],o[1],o[2],o[3]);
        *(float4*)&Cb[(size_t)(m0+i)*CD + n0+4] = make_float4(o[4],o[5],o[6],o[7]);
    }
}

// ================= launch =================
extern "C" void kernel_launch(void* const* d_in, const int* in_sizes, int n_in,
                              void* d_out, int out_size)
{
    const float* x   = (const float*)d_in[0];
    const float* W1m = (const float*)d_in[1];
    const float* b1m = (const float*)d_in[2];
    const float* W2m = (const float*)d_in[3];
    const float* b2m = (const float*)d_in[4];
    const float* W1u = (const float*)d_in[5];
    const float* b1u = (const float*)d_in[6];
    const float* W2u = (const float*)d_in[7];
    const float* b2u = (const float*)d_in[8];
    float* out = (float*)d_out;

    float *p_Am=nullptr, *p_Bm=nullptr, *p_R=nullptr, *p_hagg=nullptr, *p_H=nullptr;
    cudaGetSymbolAddress((void**)&p_Am,   g_Am);
    cudaGetSymbolAddress((void**)&p_Bm,   g_Bm);
    cudaGetSymbolAddress((void**)&p_R,    g_R);
    cudaGetSymbolAddress((void**)&p_hagg, g_hagg);
    cudaGetSymbolAddress((void**)&p_H,    g_H);

    static cudaStream_t s2 = nullptr;
    static cudaEvent_t evSim[NCHUNK], evTk[NCHUNK], evFork;
    if (!s2){
        cudaStreamCreateWithFlags(&s2, cudaStreamNonBlocking);
        cudaEventCreateWithFlags(&evFork, cudaEventDisableTiming);
        for (int i = 0; i < NCHUNK; i++){
            cudaEventCreateWithFlags(&evSim[i], cudaEventDisableTiming);
            cudaEventCreateWithFlags(&evTk[i],  cudaEventDisableTiming);
        }
    }

    // smem: max(operand tiles 2*2*BTILE*2B = 73728, epilogue 128*133*4+1024 = 69120)
    const int SIM_SMEM = 4 * BTILE * (int)sizeof(__nv_bfloat16);   // 73728 B
    cudaFuncSetAttribute(sim_mma_kernel, cudaFuncAttributeMaxDynamicSharedMemorySize, SIM_SMEM);

    cudaStream_t st = 0;

    rownorm_split_kernel<<<NPTS, 256, 0, st>>>(x);

    // fork s2
    cudaEventRecord(evFork, st);
    cudaStreamWaitEvent(s2, evFork, 0);

    // A_msg / B_msg on s2 (overlap with sim)
    mlp_gemm_kernel<<<dim3(2,128), 256, 0, s2>>>(x, nullptr, W1m,          16, b1m, 1.f, 0, nullptr, p_Am);
    mlp_gemm_kernel<<<dim3(2,128), 256, 0, s2>>>(x, nullptr, W1m + 256*CD, 16, nullptr, 0.f, 0, nullptr, p_Bm);

    // band-ordered symmetric sim (st) + per-band topk (s2)
    for (int c = 0; c < NCHUNK; c++){
        const int cBase = c * 16;                 // tile-row offset (128-row tiles)
        const int gw = 128 - cBase;               // J range width
        sim_mma_kernel<<<dim3(gw, 16), 256, SIM_SMEM, st>>>(cBase);
        cudaEventRecord(evSim[c], st);
        cudaStreamWaitEvent(s2, evSim[c], 0);
        topk_kernel<<<CHUNK, 256, 0, s2>>>(c*CHUNK);
        cudaEventRecord(evTk[c], s2);
    }
    cudaStreamWaitEvent(st, evTk[NCHUNK-1], 0);

    // R_i = sum_j relu(A_i + B_j)
    gather_relu_sum_kernel<<<NPTS, 256, 0, st>>>();

    // h_agg = R @ W2_msg + 20*b2_msg
    mlp_gemm_kernel<<<dim3(2,128), 256, 0, st>>>(p_R, nullptr, W2m, 16, b2m, (float)TOPK, 0, nullptr, p_hagg);

    // H = relu(x @ W1u[0:256] + h_agg @ W1u[256:512] + b1u)
    mlp_gemm_kernel<<<dim3(2,128), 256, 0, st>>>(x, p_hagg, W1u, 32, b1u, 1.f, 1, nullptr, p_H);

    // out = x + H @ W2_upd + b2_upd
    mlp_gemm_kernel<<<dim3(2,128), 256, 0, st>>>(p_H, nullptr, W2u, 16, b2u, 1.f, 0, x, out);
}